// round 1
// baseline (speedup 1.0000x reference)
#include <cuda_runtime.h>
#include <cstddef>

#define Bz 1024
#define Tz 64
#define Dz 512
#define Hz 512
#define G4 2048   // 4*H
#define Kz 512    // inner dim for both GEMMs

// ---------------- scratch (static __device__, allocation-free) ----------------
__device__ float g_attn[Bz * Dz];                       // 2 MB
__device__ float g_gx[(size_t)Bz * Tz * G4];            // 512 MB: precomputed x-gates
__device__ float g_h[Bz * Hz];                          // 2 MB
__device__ float g_c[Bz * Hz];                          // 2 MB
__device__ float g_hw[(size_t)Bz * G4];                 // 8 MB: h @ W_hh^T per step

// ---------------- packed f32x2 helpers (Blackwell) ----------------
__device__ __forceinline__ unsigned long long pack2(float lo, float hi) {
    unsigned long long r;
    asm("mov.b64 %0, {%1, %2};" : "=l"(r) : "f"(lo), "f"(hi));
    return r;
}
__device__ __forceinline__ void ffma2(unsigned long long& acc, unsigned long long a,
                                      unsigned long long b) {
    asm("fma.rn.f32x2 %0, %1, %2, %0;" : "+l"(acc) : "l"(a), "l"(b));
}

// ---------------- init h = c = 0 ----------------
__global__ void init_hc_kernel() {
    int i = blockIdx.x * blockDim.x + threadIdx.x;
    if (i < Bz * Hz) { g_h[i] = 0.f; g_c[i] = 0.f; }
}

// ---------------- attn = softmax_d( sum_t x[b,t,d] * w_x[t] ) ----------------
// One block per batch row b, 512 threads (one per d).
__global__ void attn_kernel(const float* __restrict__ x, const float* __restrict__ w_attn) {
    int b = blockIdx.x;
    int d = threadIdx.x;
    __shared__ float wxs[Tz];
    __shared__ float red[Dz];
    if (d < Tz) wxs[d] = w_attn[2 * Hz + d];
    __syncthreads();

    const float* xb = x + (size_t)b * Tz * Dz + d;
    float acc = 0.f;
#pragma unroll 8
    for (int t = 0; t < Tz; t++) acc = fmaf(xb[(size_t)t * Dz], wxs[t], acc);

    red[d] = acc;
    __syncthreads();
    for (int s = 256; s > 0; s >>= 1) {
        if (d < s) red[d] = fmaxf(red[d], red[d + s]);
        __syncthreads();
    }
    float m = red[0];
    __syncthreads();
    float e = expf(acc - m);
    red[d] = e;
    __syncthreads();
    for (int s = 256; s > 0; s >>= 1) {
        if (d < s) red[d] += red[d + s];
        __syncthreads();
    }
    g_attn[b * Dz + d] = e / red[0];
}

// ---------------- wx[b,t,d] = attn[b,d] * x[b,t,d]  -> input_weighted output ----------------
__global__ void wx_kernel(const float4* __restrict__ x4, float4* __restrict__ ow) {
    int i = blockIdx.x * blockDim.x + threadIdx.x;   // over B*T*D/4
    size_t e0 = (size_t)i * 4;
    int b = (int)(e0 >> 15);          // / (T*D) = 32768
    int d = (int)(e0 & (Dz - 1));     // % 512
    float4 xv = x4[i];
    float4 a = *(const float4*)(g_attn + (size_t)b * Dz + d);
    ow[i] = make_float4(xv.x * a.x, xv.y * a.y, xv.z * a.z, xv.w * a.w);
}

// ---------------- NT GEMM: C[M,2048] = A[M,512] * W[2048,512]^T (+ b1 + b2) ----------------
// 128x128 tile, K-tile 16, 256 threads, 8x8 per thread with packed f32x2 FFMA.
template <bool BIAS>
__device__ __forceinline__ void gemm_body(const float* __restrict__ A,
                                          const float* __restrict__ W,
                                          const float* __restrict__ b1,
                                          const float* __restrict__ b2,
                                          float* __restrict__ C) {
    __shared__ __align__(16) float As[16][132];
    __shared__ __align__(16) float Bs[16][132];

    const int tid = threadIdx.x;
    const int bm = blockIdx.y, bn = blockIdx.x;
    const int tx = tid & 15, ty = tid >> 4;

    unsigned long long acc[8][4];
#pragma unroll
    for (int i = 0; i < 8; i++)
#pragma unroll
        for (int j = 0; j < 4; j++) acc[i][j] = 0ULL;

    const float* Ab = A + (size_t)bm * 128 * Kz;
    const float* Bb = W + (size_t)bn * 128 * Kz;

    const int row0 = tid >> 2;         // 0..63
    const int c4 = (tid & 3) << 2;     // 0,4,8,12

    for (int k0 = 0; k0 < Kz; k0 += 16) {
#pragma unroll
        for (int l = 0; l < 2; l++) {
            int row = row0 + l * 64;
            float4 av = *(const float4*)(Ab + (size_t)row * Kz + k0 + c4);
            As[c4 + 0][row] = av.x; As[c4 + 1][row] = av.y;
            As[c4 + 2][row] = av.z; As[c4 + 3][row] = av.w;
            float4 bv = *(const float4*)(Bb + (size_t)row * Kz + k0 + c4);
            Bs[c4 + 0][row] = bv.x; Bs[c4 + 1][row] = bv.y;
            Bs[c4 + 2][row] = bv.z; Bs[c4 + 3][row] = bv.w;
        }
        __syncthreads();
#pragma unroll
        for (int k = 0; k < 16; k++) {
            float4 a0 = *(const float4*)&As[k][ty * 8];
            float4 a1 = *(const float4*)&As[k][ty * 8 + 4];
            ulonglong2 bq0 = *(const ulonglong2*)&Bs[k][tx * 8];
            ulonglong2 bq1 = *(const ulonglong2*)&Bs[k][tx * 8 + 4];
            unsigned long long bb0 = bq0.x, bb1 = bq0.y, bb2 = bq1.x, bb3 = bq1.y;
            float av[8] = {a0.x, a0.y, a0.z, a0.w, a1.x, a1.y, a1.z, a1.w};
#pragma unroll
            for (int i = 0; i < 8; i++) {
                unsigned long long ad = pack2(av[i], av[i]);
                ffma2(acc[i][0], ad, bb0);
                ffma2(acc[i][1], ad, bb1);
                ffma2(acc[i][2], ad, bb2);
                ffma2(acc[i][3], ad, bb3);
            }
        }
        __syncthreads();
    }

    // epilogue
    float bias[8];
    if (BIAS) {
#pragma unroll
        for (int j = 0; j < 8; j++) {
            int col = bn * 128 + tx * 8 + j;
            bias[j] = b1[col] + b2[col];
        }
    }
    float* Crow = C + (size_t)(bm * 128 + ty * 8) * G4 + bn * 128 + tx * 8;
#pragma unroll
    for (int i = 0; i < 8; i++) {
        float out[8];
#pragma unroll
        for (int j = 0; j < 4; j++) {
            float2 v = *reinterpret_cast<float2*>(&acc[i][j]);
            out[2 * j] = v.x; out[2 * j + 1] = v.y;
        }
        if (BIAS) {
#pragma unroll
            for (int j = 0; j < 8; j++) out[j] += bias[j];
        }
        *(float4*)(Crow + (size_t)i * G4) = make_float4(out[0], out[1], out[2], out[3]);
        *(float4*)(Crow + (size_t)i * G4 + 4) = make_float4(out[4], out[5], out[6], out[7]);
    }
}

__global__ void __launch_bounds__(256, 2)
gemm_x_kernel(const float* __restrict__ A, const float* __restrict__ W,
              const float* __restrict__ b1, const float* __restrict__ b2) {
    gemm_body<true>(A, W, b1, b2, g_gx);
}

__global__ void __launch_bounds__(256, 2)
gemm_h_kernel(const float* __restrict__ W) {
    gemm_body<false>(g_h, W, nullptr, nullptr, g_hw);
}

// ---------------- LSTM pointwise step ----------------
__global__ void lstm_step_kernel(float* __restrict__ out_enc, int t) {
    int i = blockIdx.x * blockDim.x + threadIdx.x;   // over B*H
    int b = i >> 9;
    int hh = i & (Hz - 1);
    const float* gx = g_gx + ((size_t)b * Tz + t) * G4;
    const float* hw = g_hw + (size_t)b * G4;
    float gi = gx[hh] + hw[hh];
    float gf = gx[Hz + hh] + hw[Hz + hh];
    float gg = gx[2 * Hz + hh] + hw[2 * Hz + hh];
    float go = gx[3 * Hz + hh] + hw[3 * Hz + hh];
    float si = 1.f / (1.f + expf(-gi));
    float sf = 1.f / (1.f + expf(-gf));
    float so = 1.f / (1.f + expf(-go));
    float tg = tanhf(gg);
    float c2 = sf * g_c[i] + si * tg;
    float h2 = so * tanhf(c2);
    g_c[i] = c2;
    g_h[i] = h2;
    out_enc[((size_t)b * Tz + t) * Hz + hh] = h2;
}

// ---------------- launch ----------------
extern "C" void kernel_launch(void* const* d_in, const int* in_sizes, int n_in,
                              void* d_out, int out_size) {
    const float* x      = (const float*)d_in[0];   // (B,T,D)
    const float* w_ih   = (const float*)d_in[1];   // (4H,D)
    const float* w_hh   = (const float*)d_in[2];   // (4H,H)
    const float* b_ih   = (const float*)d_in[3];   // (4H)
    const float* b_hh   = (const float*)d_in[4];   // (4H)
    const float* w_attn = (const float*)d_in[5];   // (1, 2H+T)
    // d_in[6] = b_attn: cancels in softmax (per-row constant) -> unused
    (void)in_sizes; (void)n_in; (void)out_size;

    float* out_w   = (float*)d_out;                       // input_weighted (B,T,D)
    float* out_enc = out_w + (size_t)Bz * Tz * Dz;        // input_encoded (B,T,H)

    init_hc_kernel<<<(Bz * Hz + 255) / 256, 256>>>();
    attn_kernel<<<Bz, Dz>>>(x, w_attn);
    wx_kernel<<<(Bz * Tz * Dz / 4 + 255) / 256, 256>>>((const float4*)x, (float4*)out_w);

    // big parallel GEMM: G_x = WX @ W_ih^T + (b_ih + b_hh);  M = B*T = 65536
    gemm_x_kernel<<<dim3(G4 / 128, (Bz * Tz) / 128), 256>>>(out_w, w_ih, b_ih, b_hh);

    // sequential recurrence
    for (int t = 0; t < Tz; t++) {
        gemm_h_kernel<<<dim3(G4 / 128, Bz / 128), 256>>>(w_hh);
        lstm_step_kernel<<<(Bz * Hz + 255) / 256, 256>>>(out_enc, t);
    }
}

// round 3
// speedup vs baseline: 1.8553x; 1.8553x over previous
#include <cuda_runtime.h>
#include <cuda_bf16.h>
#include <cstdint>
#include <cstddef>

#define Bz 1024
#define Tz 64
#define Dz 512
#define Hz 512
#define G4 2048
#define Kz 512

// ---------------- scratch (static __device__, allocation-free) ----------------
__device__ __align__(256) float g_attn[Bz * Dz];
__device__ __align__(256) float g_gx[(size_t)Bz * Tz * G4];            // 512 MB, interleaved cols
__device__ __align__(256) float g_c[Bz * Hz];
__device__ __align__(256) __nv_bfloat16 g_h_hi[Bz * Hz];
__device__ __align__(256) __nv_bfloat16 g_h_lo[Bz * Hz];
__device__ __align__(256) __nv_bfloat16 g_wx_hi[(size_t)Bz * Tz * Dz];
__device__ __align__(256) __nv_bfloat16 g_wx_lo[(size_t)Bz * Tz * Dz];
__device__ __align__(256) __nv_bfloat16 g_wih_hi[G4 * Dz];             // interleaved rows
__device__ __align__(256) __nv_bfloat16 g_wih_lo[G4 * Dz];
__device__ __align__(256) __nv_bfloat16 g_whh_hi[G4 * Hz];
__device__ __align__(256) __nv_bfloat16 g_whh_lo[G4 * Hz];
__device__ __align__(256) float g_bias[G4];                            // interleaved cols

// ---------------- helpers ----------------
__device__ __forceinline__ uint32_t smem_u32(const void* p) {
    uint32_t a;
    asm("{ .reg .u64 t; cvta.to.shared.u64 t, %1; cvt.u32.u64 %0, t; }" : "=r"(a) : "l"(p));
    return a;
}
__device__ __forceinline__ float sigm(float x) { return 1.f / (1.f + __expf(-x)); }
__device__ __forceinline__ float tanh_f(float x) { return 2.f / (1.f + __expf(-2.f * x)) - 1.f; }
__device__ __forceinline__ void split_bf16(float v, __nv_bfloat16& hi, __nv_bfloat16& lo) {
    hi = __float2bfloat16(v);
    lo = __float2bfloat16(v - __bfloat162float(hi));
}

#define LDSM4(r, addr)                                                      \
    asm volatile("ldmatrix.sync.aligned.m8n8.x4.shared.b16 {%0,%1,%2,%3}, [%4];" \
                 : "=r"((r)[0]), "=r"((r)[1]), "=r"((r)[2]), "=r"((r)[3])   \
                 : "r"(addr))

#define MMA(d, a, b0, b1)                                                   \
    asm volatile("mma.sync.aligned.m16n8k16.row.col.f32.bf16.bf16.f32 "     \
                 "{%0,%1,%2,%3}, {%4,%5,%6,%7}, {%8,%9}, {%0,%1,%2,%3};"    \
                 : "+f"((d)[0]), "+f"((d)[1]), "+f"((d)[2]), "+f"((d)[3])   \
                 : "r"((a)[0]), "r"((a)[1]), "r"((a)[2]), "r"((a)[3]),      \
                   "r"(b0), "r"(b1))

#define CP_ASYNC16(s, g) \
    asm volatile("cp.async.cg.shared.global [%0], [%1], 16;" :: "r"(s), "l"(g))
#define CP_COMMIT() asm volatile("cp.async.commit_group;" ::: "memory")
#define CP_WAIT(n)  asm volatile("cp.async.wait_group %0;" :: "n"(n) : "memory")

// smem tile: 128 rows x 32 halves, pitch 40 halves (80 B, 16B-aligned rows)
#define PITCH_H 40
#define MAT_BYTES (128 * PITCH_H * 2)      // 10240
#define STAGE_BYTES (4 * MAT_BYTES)        // 40960: [Ahi, Alo, Bhi, Blo]
#define SMEM_SZ (2 * STAGE_BYTES)          // 81920

// ---------------- init ----------------
__global__ void init_kernel() {
    int i = blockIdx.x * blockDim.x + threadIdx.x;
    if (i < Bz * Hz) {
        g_c[i] = 0.f;
        g_h_hi[i] = __float2bfloat16(0.f);
        g_h_lo[i] = __float2bfloat16(0.f);
    }
}

// ---------------- attn = softmax_d( sum_t x[b,t,d] * w_x[t] ) ----------------
__global__ void attn_kernel(const float* __restrict__ x, const float* __restrict__ w_attn) {
    int b = blockIdx.x;
    int d = threadIdx.x;
    __shared__ float wxs[Tz];
    __shared__ float red[Dz];
    if (d < Tz) wxs[d] = w_attn[2 * Hz + d];
    __syncthreads();
    const float* xb = x + (size_t)b * Tz * Dz + d;
    float acc = 0.f;
#pragma unroll 8
    for (int t = 0; t < Tz; t++) acc = fmaf(xb[(size_t)t * Dz], wxs[t], acc);
    red[d] = acc;
    __syncthreads();
    for (int s = 256; s > 0; s >>= 1) {
        if (d < s) red[d] = fmaxf(red[d], red[d + s]);
        __syncthreads();
    }
    float m = red[0];
    __syncthreads();
    float e = __expf(acc - m);
    red[d] = e;
    __syncthreads();
    for (int s = 256; s > 0; s >>= 1) {
        if (d < s) red[d] += red[d + s];
        __syncthreads();
    }
    g_attn[b * Dz + d] = e / red[0];
}

// ---------------- wx = attn * x (fp32 output + bf16 hi/lo split) ----------------
__global__ void wx_kernel(const float4* __restrict__ x4, float4* __restrict__ ow) {
    int i = blockIdx.x * blockDim.x + threadIdx.x;
    size_t e0 = (size_t)i * 4;
    int b = (int)(e0 >> 15);
    int d = (int)(e0 & (Dz - 1));
    float4 xv = x4[i];
    float4 a = *(const float4*)(g_attn + (size_t)b * Dz + d);
    float4 wv = make_float4(xv.x * a.x, xv.y * a.y, xv.z * a.z, xv.w * a.w);
    ow[i] = wv;
    __nv_bfloat16 h0, l0, h1, l1, h2, l2, h3, l3;
    split_bf16(wv.x, h0, l0); split_bf16(wv.y, h1, l1);
    split_bf16(wv.z, h2, l2); split_bf16(wv.w, h3, l3);
    *(__nv_bfloat162*)(g_wx_hi + e0)     = __nv_bfloat162(h0, h1);
    *(__nv_bfloat162*)(g_wx_hi + e0 + 2) = __nv_bfloat162(h2, h3);
    *(__nv_bfloat162*)(g_wx_lo + e0)     = __nv_bfloat162(l0, l1);
    *(__nv_bfloat162*)(g_wx_lo + e0 + 2) = __nv_bfloat162(l2, l3);
}

// ---------------- weight prep: interleave rows + bf16 hi/lo split ----------------
// new row nr for (gate g, unit u): nr = (u/8)*32 + g*8 + (u%8)
__global__ void prep_w_kernel(const float* __restrict__ wih, const float* __restrict__ whh,
                              const float* __restrict__ bih, const float* __restrict__ bhh) {
    int i = blockIdx.x * blockDim.x + threadIdx.x;
    if (i < G4 * Kz) {
        int row = i >> 9;
        int k = i & 511;
        int g = row >> 9;
        int u = row & 511;
        int nr = ((u >> 3) << 5) + (g << 3) + (u & 7);
        __nv_bfloat16 hi, lo;
        split_bf16(wih[i], hi, lo);
        g_wih_hi[nr * 512 + k] = hi;
        g_wih_lo[nr * 512 + k] = lo;
        split_bf16(whh[i], hi, lo);
        g_whh_hi[nr * 512 + k] = hi;
        g_whh_lo[nr * 512 + k] = lo;
        if (i < G4) {
            int gg = i >> 9, uu = i & 511;
            int nb = ((uu >> 3) << 5) + (gg << 3) + (uu & 7);
            g_bias[nb] = bih[i] + bhh[i];
        }
    }
}

// ---------------- bf16x3 mma.sync GEMM, 128x128 tile, fused LSTM epilogue ----------------
template <int LSTM>
__global__ void __launch_bounds__(256)
gemm_mma(float* __restrict__ out_enc, int t) {
    extern __shared__ char smem[];
    const int tid = threadIdx.x;
    const int lane = tid & 31, wid = tid >> 5;
    const int wm = wid >> 2, wn = wid & 3;       // warps: 2 (M) x 4 (N)
    const int bn = blockIdx.x, bm = blockIdx.y;

    const __nv_bfloat16* Ahi = (LSTM ? g_h_hi : g_wx_hi) + (size_t)bm * 128 * Kz;
    const __nv_bfloat16* Alo = (LSTM ? g_h_lo : g_wx_lo) + (size_t)bm * 128 * Kz;
    const __nv_bfloat16* Bhi = (LSTM ? g_whh_hi : g_wih_hi) + (size_t)bn * 128 * Kz;
    const __nv_bfloat16* Blo = (LSTM ? g_whh_lo : g_wih_lo) + (size_t)bn * 128 * Kz;
    const __nv_bfloat16* srcs[4] = {Ahi, Alo, Bhi, Blo};

    float acc[4][4][4];
#pragma unroll
    for (int a = 0; a < 4; a++)
#pragma unroll
        for (int b = 0; b < 4; b++)
#pragma unroll
            for (int cidx = 0; cidx < 4; cidx++) acc[a][b][cidx] = 0.f;

    // ---- prefetch lambda: 4 matrices x 512 16B-chunks, 2 chunks/thread/matrix ----
    auto prefetch = [&](int kt, int stage) {
        int k0 = kt * 32;
        char* sbase = smem + stage * STAGE_BYTES;
#pragma unroll
        for (int m = 0; m < 4; m++) {
#pragma unroll
            for (int j = 0; j < 2; j++) {
                int ci = tid * 2 + j;
                int row = ci >> 2, c16 = ci & 3;
                const void* g = srcs[m] + (size_t)row * Kz + k0 + c16 * 8;
                uint32_t s = smem_u32(sbase + m * MAT_BYTES + row * 80 + c16 * 16);
                CP_ASYNC16(s, g);
            }
        }
    };

    prefetch(0, 0);
    CP_COMMIT();

    for (int kt = 0; kt < 16; kt++) {
        if (kt + 1 < 16) {
            prefetch(kt + 1, (kt + 1) & 1);
            CP_COMMIT();
            CP_WAIT(1);
        } else {
            CP_WAIT(0);
        }
        __syncthreads();

        char* sbase = smem + (kt & 1) * STAGE_BYTES;
#pragma unroll
        for (int kk = 0; kk < 2; kk++) {
            uint32_t ahi[4][4], alo[4][4], bhi[2][4], blo[2][4];
            uint32_t a_off = (uint32_t)((wm * 64 + (lane & 15)) * 80 + (lane >> 4) * 16 + kk * 32);
#pragma unroll
            for (int mi = 0; mi < 4; mi++) {
                LDSM4(ahi[mi], smem_u32(sbase + 0 * MAT_BYTES + a_off + mi * 16 * 80));
                LDSM4(alo[mi], smem_u32(sbase + 1 * MAT_BYTES + a_off + mi * 16 * 80));
            }
            uint32_t b_off = (uint32_t)((wn * 32 + (lane >> 4) * 8 + (lane & 7)) * 80 +
                                        ((lane >> 3) & 1) * 16 + kk * 32);
#pragma unroll
            for (int p = 0; p < 2; p++) {
                LDSM4(bhi[p], smem_u32(sbase + 2 * MAT_BYTES + b_off + p * 16 * 80));
                LDSM4(blo[p], smem_u32(sbase + 3 * MAT_BYTES + b_off + p * 16 * 80));
            }
#pragma unroll
            for (int mi = 0; mi < 4; mi++)
#pragma unroll
                for (int ni = 0; ni < 4; ni++)
                    MMA(acc[mi][ni], ahi[mi], bhi[ni >> 1][(ni & 1) * 2], bhi[ni >> 1][(ni & 1) * 2 + 1]);
#pragma unroll
            for (int mi = 0; mi < 4; mi++)
#pragma unroll
                for (int ni = 0; ni < 4; ni++)
                    MMA(acc[mi][ni], ahi[mi], blo[ni >> 1][(ni & 1) * 2], blo[ni >> 1][(ni & 1) * 2 + 1]);
#pragma unroll
            for (int mi = 0; mi < 4; mi++)
#pragma unroll
                for (int ni = 0; ni < 4; ni++)
                    MMA(acc[mi][ni], alo[mi], bhi[ni >> 1][(ni & 1) * 2], bhi[ni >> 1][(ni & 1) * 2 + 1]);
        }
        __syncthreads();
    }

    // ---- epilogue ----
    const int r0 = bm * 128 + wm * 64 + (lane >> 2);
    if (!LSTM) {
#pragma unroll
        for (int ni = 0; ni < 4; ni++) {
            int c = bn * 128 + wn * 32 + ni * 8 + (lane & 3) * 2;
            float2 bi = *(const float2*)(g_bias + c);
#pragma unroll
            for (int mi = 0; mi < 4; mi++) {
                int r = r0 + mi * 16;
                *(float2*)(g_gx + (size_t)r * G4 + c) =
                    make_float2(acc[mi][ni][0] + bi.x, acc[mi][ni][1] + bi.y);
                *(float2*)(g_gx + (size_t)(r + 8) * G4 + c) =
                    make_float2(acc[mi][ni][2] + bi.x, acc[mi][ni][3] + bi.y);
            }
        }
    } else {
        const int U = (bn * 4 + wn) * 8 + (lane & 3) * 2;
#pragma unroll
        for (int mi = 0; mi < 4; mi++) {
#pragma unroll
            for (int half = 0; half < 2; half++) {
                int m = r0 + mi * 16 + half * 8;
                int j0 = half * 2;
                const float* gxr = g_gx + ((size_t)m * Tz + t) * G4 + bn * 128 + wn * 32 + (lane & 3) * 2;
                float2 gI = *(const float2*)(gxr + 0);
                float2 gF = *(const float2*)(gxr + 8);
                float2 gG = *(const float2*)(gxr + 16);
                float2 gO = *(const float2*)(gxr + 24);
                float2 cv = *(const float2*)(g_c + (size_t)m * Hz + U);
                float gi0 = acc[mi][0][j0] + gI.x, gi1 = acc[mi][0][j0 + 1] + gI.y;
                float gf0 = acc[mi][1][j0] + gF.x, gf1 = acc[mi][1][j0 + 1] + gF.y;
                float gg0 = acc[mi][2][j0] + gG.x, gg1 = acc[mi][2][j0 + 1] + gG.y;
                float go0 = acc[mi][3][j0] + gO.x, go1 = acc[mi][3][j0 + 1] + gO.y;
                float c20 = sigm(gf0) * cv.x + sigm(gi0) * tanh_f(gg0);
                float c21 = sigm(gf1) * cv.y + sigm(gi1) * tanh_f(gg1);
                float h20 = sigm(go0) * tanh_f(c20);
                float h21 = sigm(go1) * tanh_f(c21);
                *(float2*)(g_c + (size_t)m * Hz + U) = make_float2(c20, c21);
                *(float2*)(out_enc + ((size_t)m * Tz + t) * Hz + U) = make_float2(h20, h21);
                __nv_bfloat16 hh0, hl0, hh1, hl1;
                split_bf16(h20, hh0, hl0);
                split_bf16(h21, hh1, hl1);
                *(__nv_bfloat162*)(g_h_hi + (size_t)m * Hz + U) = __nv_bfloat162(hh0, hh1);
                *(__nv_bfloat162*)(g_h_lo + (size_t)m * Hz + U) = __nv_bfloat162(hl0, hl1);
            }
        }
    }
}

// ---------------- launch ----------------
extern "C" void kernel_launch(void* const* d_in, const int* in_sizes, int n_in,
                              void* d_out, int out_size) {
    const float* x      = (const float*)d_in[0];
    const float* w_ih   = (const float*)d_in[1];
    const float* w_hh   = (const float*)d_in[2];
    const float* b_ih   = (const float*)d_in[3];
    const float* b_hh   = (const float*)d_in[4];
    const float* w_attn = (const float*)d_in[5];
    (void)in_sizes; (void)n_in; (void)out_size;

    float* out_w   = (float*)d_out;
    float* out_enc = out_w + (size_t)Bz * Tz * Dz;

    static int attr_done = 0;
    if (!attr_done) {
        cudaFuncSetAttribute(gemm_mma<0>, cudaFuncAttributeMaxDynamicSharedMemorySize, SMEM_SZ);
        cudaFuncSetAttribute(gemm_mma<1>, cudaFuncAttributeMaxDynamicSharedMemorySize, SMEM_SZ);
        attr_done = 1;
    }

    init_kernel<<<(Bz * Hz + 255) / 256, 256>>>();
    attn_kernel<<<Bz, Dz>>>(x, w_attn);
    wx_kernel<<<(Bz * Tz * Dz / 4 + 255) / 256, 256>>>((const float4*)x, (float4*)out_w);
    prep_w_kernel<<<(G4 * Kz + 255) / 256, 256>>>(w_ih, w_hh, b_ih, b_hh);

    // G_x = WX @ W_ih'^T + bias   (M = 65536, N = 2048 interleaved, K = 512)
    gemm_mma<0><<<dim3(G4 / 128, (Bz * Tz) / 128), 256, SMEM_SZ>>>(nullptr, 0);

    // recurrence: h-GEMM with fused LSTM pointwise epilogue
    for (int t = 0; t < Tz; t++) {
        gemm_mma<1><<<dim3(G4 / 128, Bz / 128), 256, SMEM_SZ>>>(out_enc, t);
    }
}

// round 4
// speedup vs baseline: 3.0830x; 1.6617x over previous
#include <cuda_runtime.h>
#include <cuda_bf16.h>
#include <cstdint>
#include <cstddef>

#define Bz 1024
#define Tz 64
#define Dz 512
#define Hz 512
#define G4 2048
#define Kz 512

// ---------------- scratch (static __device__, allocation-free) ----------------
__device__ __align__(256) float g_attn[Bz * Dz];
__device__ __align__(256) float g_gx[(size_t)Bz * Tz * G4];            // 512 MB, interleaved cols
__device__ __align__(256) float g_c[Bz * Hz];
__device__ __align__(256) __nv_bfloat16 g_h_hi[Bz * Hz];
__device__ __align__(256) __nv_bfloat16 g_h_lo[Bz * Hz];
__device__ __align__(256) __nv_bfloat16 g_wx_hi[(size_t)Bz * Tz * Dz];
__device__ __align__(256) __nv_bfloat16 g_wx_lo[(size_t)Bz * Tz * Dz];
__device__ __align__(256) __nv_bfloat16 g_wih_hi[G4 * Dz];             // interleaved rows
__device__ __align__(256) __nv_bfloat16 g_wih_lo[G4 * Dz];
__device__ __align__(256) __nv_bfloat16 g_whh_hi[G4 * Hz];
__device__ __align__(256) __nv_bfloat16 g_whh_lo[G4 * Hz];
__device__ __align__(256) float g_bias[G4];                            // interleaved cols
__device__ unsigned g_bar[8];                                          // bm-group barriers

// ---------------- helpers ----------------
__device__ __forceinline__ uint32_t smem_u32(const void* p) {
    uint32_t a;
    asm("{ .reg .u64 t; cvta.to.shared.u64 t, %1; cvt.u32.u64 %0, t; }" : "=r"(a) : "l"(p));
    return a;
}
__device__ __forceinline__ unsigned ld_acq(const unsigned* p) {
    unsigned v;
    asm volatile("ld.acquire.gpu.global.u32 %0, [%1];" : "=r"(v) : "l"(p));
    return v;
}
__device__ __forceinline__ float sigm(float x) { return 1.f / (1.f + __expf(-x)); }
__device__ __forceinline__ float tanh_f(float x) { return 2.f / (1.f + __expf(-2.f * x)) - 1.f; }
__device__ __forceinline__ void split_bf16(float v, __nv_bfloat16& hi, __nv_bfloat16& lo) {
    hi = __float2bfloat16(v);
    lo = __float2bfloat16(v - __bfloat162float(hi));
}

#define LDSM4(r, addr)                                                      \
    asm volatile("ldmatrix.sync.aligned.m8n8.x4.shared.b16 {%0,%1,%2,%3}, [%4];" \
                 : "=r"((r)[0]), "=r"((r)[1]), "=r"((r)[2]), "=r"((r)[3])   \
                 : "r"(addr))

#define MMA(d, a, b0, b1)                                                   \
    asm volatile("mma.sync.aligned.m16n8k16.row.col.f32.bf16.bf16.f32 "     \
                 "{%0,%1,%2,%3}, {%4,%5,%6,%7}, {%8,%9}, {%0,%1,%2,%3};"    \
                 : "+f"((d)[0]), "+f"((d)[1]), "+f"((d)[2]), "+f"((d)[3])   \
                 : "r"((a)[0]), "r"((a)[1]), "r"((a)[2]), "r"((a)[3]),      \
                   "r"(b0), "r"(b1))

#define CP_ASYNC16(s, g) \
    asm volatile("cp.async.cg.shared.global [%0], [%1], 16;" :: "r"(s), "l"(g))
#define CP_COMMIT() asm volatile("cp.async.commit_group;" ::: "memory")
#define CP_WAIT(n)  asm volatile("cp.async.wait_group %0;" :: "n"(n) : "memory")

// smem tile: 128 rows x 32 halves, pitch 40 halves (80 B, 16B-aligned rows)
#define PITCH_H 40
#define MAT_BYTES (128 * PITCH_H * 2)      // 10240
#define STAGE_BYTES (4 * MAT_BYTES)        // 40960: [Ahi, Alo, Bhi, Blo]
#define SMEM_SZ (2 * STAGE_BYTES)          // 81920

// ---------------- init ----------------
__global__ void init_kernel() {
    int i = blockIdx.x * blockDim.x + threadIdx.x;
    if (i < Bz * Hz) {
        g_c[i] = 0.f;
        g_h_hi[i] = __float2bfloat16(0.f);
        g_h_lo[i] = __float2bfloat16(0.f);
    }
    if (i < 8) g_bar[i] = 0u;
}

// ---------------- attn = softmax_d( sum_t x[b,t,d] * w_x[t] ) ----------------
__global__ void attn_kernel(const float* __restrict__ x, const float* __restrict__ w_attn) {
    int b = blockIdx.x;
    int d = threadIdx.x;
    __shared__ float wxs[Tz];
    __shared__ float red[Dz];
    if (d < Tz) wxs[d] = w_attn[2 * Hz + d];
    __syncthreads();
    const float* xb = x + (size_t)b * Tz * Dz + d;
    float acc = 0.f;
#pragma unroll 8
    for (int t = 0; t < Tz; t++) acc = fmaf(xb[(size_t)t * Dz], wxs[t], acc);
    red[d] = acc;
    __syncthreads();
    for (int s = 256; s > 0; s >>= 1) {
        if (d < s) red[d] = fmaxf(red[d], red[d + s]);
        __syncthreads();
    }
    float m = red[0];
    __syncthreads();
    float e = __expf(acc - m);
    red[d] = e;
    __syncthreads();
    for (int s = 256; s > 0; s >>= 1) {
        if (d < s) red[d] += red[d + s];
        __syncthreads();
    }
    g_attn[b * Dz + d] = e / red[0];
}

// ---------------- wx = attn * x (fp32 output + bf16 hi/lo split) ----------------
__global__ void wx_kernel(const float4* __restrict__ x4, float4* __restrict__ ow) {
    int i = blockIdx.x * blockDim.x + threadIdx.x;
    size_t e0 = (size_t)i * 4;
    int b = (int)(e0 >> 15);
    int d = (int)(e0 & (Dz - 1));
    float4 xv = x4[i];
    float4 a = *(const float4*)(g_attn + (size_t)b * Dz + d);
    float4 wv = make_float4(xv.x * a.x, xv.y * a.y, xv.z * a.z, xv.w * a.w);
    ow[i] = wv;
    __nv_bfloat16 h0, l0, h1, l1, h2, l2, h3, l3;
    split_bf16(wv.x, h0, l0); split_bf16(wv.y, h1, l1);
    split_bf16(wv.z, h2, l2); split_bf16(wv.w, h3, l3);
    *(__nv_bfloat162*)(g_wx_hi + e0)     = __nv_bfloat162(h0, h1);
    *(__nv_bfloat162*)(g_wx_hi + e0 + 2) = __nv_bfloat162(h2, h3);
    *(__nv_bfloat162*)(g_wx_lo + e0)     = __nv_bfloat162(l0, l1);
    *(__nv_bfloat162*)(g_wx_lo + e0 + 2) = __nv_bfloat162(l2, l3);
}

// ---------------- weight prep: interleave rows + bf16 hi/lo split ----------------
// new row nr for (gate g, unit u): nr = (u/8)*32 + g*8 + (u%8)
__global__ void prep_w_kernel(const float* __restrict__ wih, const float* __restrict__ whh,
                              const float* __restrict__ bih, const float* __restrict__ bhh) {
    int i = blockIdx.x * blockDim.x + threadIdx.x;
    if (i < G4 * Kz) {
        int row = i >> 9;
        int k = i & 511;
        int g = row >> 9;
        int u = row & 511;
        int nr = ((u >> 3) << 5) + (g << 3) + (u & 7);
        __nv_bfloat16 hi, lo;
        split_bf16(wih[i], hi, lo);
        g_wih_hi[nr * 512 + k] = hi;
        g_wih_lo[nr * 512 + k] = lo;
        split_bf16(whh[i], hi, lo);
        g_whh_hi[nr * 512 + k] = hi;
        g_whh_lo[nr * 512 + k] = lo;
        if (i < G4) {
            int gg = i >> 9, uu = i & 511;
            int nb = ((uu >> 3) << 5) + (gg << 3) + (uu & 7);
            g_bias[nb] = bih[i] + bhh[i];
        }
    }
}

// ---------------- shared mainloop: 128x128 bf16x3 tile into acc ----------------
struct Frag { float a[4][4][4]; };

template <typename PF>
__device__ __forceinline__ void mma_mainloop(char* smem, int lane, int wm, int wn,
                                             float (&acc)[4][4][4], PF&& prefetch) {
#pragma unroll
    for (int a = 0; a < 4; a++)
#pragma unroll
        for (int b = 0; b < 4; b++)
#pragma unroll
            for (int cidx = 0; cidx < 4; cidx++) acc[a][b][cidx] = 0.f;

    prefetch(0, 0);
    CP_COMMIT();

    for (int kt = 0; kt < 16; kt++) {
        if (kt + 1 < 16) {
            prefetch(kt + 1, (kt + 1) & 1);
            CP_COMMIT();
            CP_WAIT(1);
        } else {
            CP_WAIT(0);
        }
        __syncthreads();

        char* sbase = smem + (kt & 1) * STAGE_BYTES;
#pragma unroll
        for (int kk = 0; kk < 2; kk++) {
            uint32_t ahi[4][4], alo[4][4], bhi[2][4], blo[2][4];
            uint32_t a_off = (uint32_t)((wm * 64 + (lane & 15)) * 80 + (lane >> 4) * 16 + kk * 32);
#pragma unroll
            for (int mi = 0; mi < 4; mi++) {
                LDSM4(ahi[mi], smem_u32(sbase + 0 * MAT_BYTES + a_off + mi * 16 * 80));
                LDSM4(alo[mi], smem_u32(sbase + 1 * MAT_BYTES + a_off + mi * 16 * 80));
            }
            uint32_t b_off = (uint32_t)((wn * 32 + (lane >> 4) * 8 + (lane & 7)) * 80 +
                                        ((lane >> 3) & 1) * 16 + kk * 32);
#pragma unroll
            for (int p = 0; p < 2; p++) {
                LDSM4(bhi[p], smem_u32(sbase + 2 * MAT_BYTES + b_off + p * 16 * 80));
                LDSM4(blo[p], smem_u32(sbase + 3 * MAT_BYTES + b_off + p * 16 * 80));
            }
#pragma unroll
            for (int mi = 0; mi < 4; mi++)
#pragma unroll
                for (int ni = 0; ni < 4; ni++)
                    MMA(acc[mi][ni], ahi[mi], bhi[ni >> 1][(ni & 1) * 2], bhi[ni >> 1][(ni & 1) * 2 + 1]);
#pragma unroll
            for (int mi = 0; mi < 4; mi++)
#pragma unroll
                for (int ni = 0; ni < 4; ni++)
                    MMA(acc[mi][ni], ahi[mi], blo[ni >> 1][(ni & 1) * 2], blo[ni >> 1][(ni & 1) * 2 + 1]);
#pragma unroll
            for (int mi = 0; mi < 4; mi++)
#pragma unroll
                for (int ni = 0; ni < 4; ni++)
                    MMA(acc[mi][ni], alo[mi], bhi[ni >> 1][(ni & 1) * 2], bhi[ni >> 1][(ni & 1) * 2 + 1]);
        }
        __syncthreads();
    }
}

// ---------------- x-GEMM: G_x = WX @ W_ih'^T + bias ----------------
__global__ void __launch_bounds__(256)
gemm_x(int dummy) {
    extern __shared__ char smem[];
    const int tid = threadIdx.x;
    const int lane = tid & 31, wid = tid >> 5;
    const int wm = wid >> 2, wn = wid & 3;
    const int bn = blockIdx.x, bm = blockIdx.y;

    const __nv_bfloat16* Ahi = g_wx_hi + (size_t)bm * 128 * Kz;
    const __nv_bfloat16* Alo = g_wx_lo + (size_t)bm * 128 * Kz;
    const __nv_bfloat16* Bhi = g_wih_hi + (size_t)bn * 128 * Kz;
    const __nv_bfloat16* Blo = g_wih_lo + (size_t)bn * 128 * Kz;
    const __nv_bfloat16* srcs[4] = {Ahi, Alo, Bhi, Blo};

    auto prefetch = [&](int kt, int stage) {
        int k0 = kt * 32;
        char* sbase = smem + stage * STAGE_BYTES;
#pragma unroll
        for (int m = 0; m < 4; m++) {
#pragma unroll
            for (int j = 0; j < 2; j++) {
                int ci = tid * 2 + j;
                int row = ci >> 2, c16 = ci & 3;
                const void* g = srcs[m] + (size_t)row * Kz + k0 + c16 * 8;
                uint32_t s = smem_u32(sbase + m * MAT_BYTES + row * 80 + c16 * 16);
                CP_ASYNC16(s, g);
            }
        }
    };

    float acc[4][4][4];
    mma_mainloop(smem, lane, wm, wn, acc, prefetch);

    const int r0 = bm * 128 + wm * 64 + (lane >> 2);
#pragma unroll
    for (int ni = 0; ni < 4; ni++) {
        int c = bn * 128 + wn * 32 + ni * 8 + (lane & 3) * 2;
        float2 bi = *(const float2*)(g_bias + c);
#pragma unroll
        for (int mi = 0; mi < 4; mi++) {
            int r = r0 + mi * 16;
            *(float2*)(g_gx + (size_t)r * G4 + c) =
                make_float2(acc[mi][ni][0] + bi.x, acc[mi][ni][1] + bi.y);
            *(float2*)(g_gx + (size_t)(r + 8) * G4 + c) =
                make_float2(acc[mi][ni][2] + bi.x, acc[mi][ni][3] + bi.y);
        }
    }
}

// ---------------- persistent recurrence: 64 steps, bm-group barriers ----------------
__global__ void __launch_bounds__(256)
gemm_rec(float* __restrict__ out_enc) {
    extern __shared__ char smem[];
    const int tid = threadIdx.x;
    const int lane = tid & 31, wid = tid >> 5;
    const int wm = wid >> 2, wn = wid & 3;
    const int bn = blockIdx.x & 15, bm = blockIdx.x >> 4;

    const __nv_bfloat16* Ahi = g_h_hi + (size_t)bm * 128 * Kz;
    const __nv_bfloat16* Alo = g_h_lo + (size_t)bm * 128 * Kz;
    const __nv_bfloat16* Bhi = g_whh_hi + (size_t)bn * 128 * Kz;
    const __nv_bfloat16* Blo = g_whh_lo + (size_t)bn * 128 * Kz;
    const __nv_bfloat16* srcs[4] = {Ahi, Alo, Bhi, Blo};

    auto prefetch = [&](int kt, int stage) {
        int k0 = kt * 32;
        char* sbase = smem + stage * STAGE_BYTES;
#pragma unroll
        for (int m = 0; m < 4; m++) {
#pragma unroll
            for (int j = 0; j < 2; j++) {
                int ci = tid * 2 + j;
                int row = ci >> 2, c16 = ci & 3;
                const void* g = srcs[m] + (size_t)row * Kz + k0 + c16 * 8;
                uint32_t s = smem_u32(sbase + m * MAT_BYTES + row * 80 + c16 * 16);
                CP_ASYNC16(s, g);
            }
        }
    };

    const int r0 = bm * 128 + wm * 64 + (lane >> 2);
    const int U = (bn * 4 + wn) * 8 + (lane & 3) * 2;

    for (int t = 0; t < Tz; t++) {
        float acc[4][4][4];
        mma_mainloop(smem, lane, wm, wn, acc, prefetch);

        // ---- fused LSTM epilogue ----
#pragma unroll
        for (int mi = 0; mi < 4; mi++) {
#pragma unroll
            for (int half = 0; half < 2; half++) {
                int m = r0 + mi * 16 + half * 8;
                int j0 = half * 2;
                const float* gxr = g_gx + ((size_t)m * Tz + t) * G4 + bn * 128 + wn * 32 + (lane & 3) * 2;
                float2 gI = *(const float2*)(gxr + 0);
                float2 gF = *(const float2*)(gxr + 8);
                float2 gG = *(const float2*)(gxr + 16);
                float2 gO = *(const float2*)(gxr + 24);
                float2 cv = *(const float2*)(g_c + (size_t)m * Hz + U);
                float gi0 = acc[mi][0][j0] + gI.x, gi1 = acc[mi][0][j0 + 1] + gI.y;
                float gf0 = acc[mi][1][j0] + gF.x, gf1 = acc[mi][1][j0 + 1] + gF.y;
                float gg0 = acc[mi][2][j0] + gG.x, gg1 = acc[mi][2][j0 + 1] + gG.y;
                float go0 = acc[mi][3][j0] + gO.x, go1 = acc[mi][3][j0 + 1] + gO.y;
                float c20 = sigm(gf0) * cv.x + sigm(gi0) * tanh_f(gg0);
                float c21 = sigm(gf1) * cv.y + sigm(gi1) * tanh_f(gg1);
                float h20 = sigm(go0) * tanh_f(c20);
                float h21 = sigm(go1) * tanh_f(c21);
                *(float2*)(g_c + (size_t)m * Hz + U) = make_float2(c20, c21);
                *(float2*)(out_enc + ((size_t)m * Tz + t) * Hz + U) = make_float2(h20, h21);
                __nv_bfloat16 hh0, hl0, hh1, hl1;
                split_bf16(h20, hh0, hl0);
                split_bf16(h21, hh1, hl1);
                *(__nv_bfloat162*)(g_h_hi + (size_t)m * Hz + U) = __nv_bfloat162(hh0, hh1);
                *(__nv_bfloat162*)(g_h_lo + (size_t)m * Hz + U) = __nv_bfloat162(hl0, hl1);
            }
        }

        // ---- bm-group barrier (16 CTAs share h rows of bm) ----
        if (t + 1 < Tz) {
            __threadfence();
            __syncthreads();
            if (tid == 0) {
                atomicAdd(&g_bar[bm], 1u);
                unsigned target = 16u * (unsigned)(t + 1);
                while (ld_acq(&g_bar[bm]) < target) { }
            }
            __syncthreads();
        }
    }
}

// ---------------- launch ----------------
extern "C" void kernel_launch(void* const* d_in, const int* in_sizes, int n_in,
                              void* d_out, int out_size) {
    const float* x      = (const float*)d_in[0];
    const float* w_ih   = (const float*)d_in[1];
    const float* w_hh   = (const float*)d_in[2];
    const float* b_ih   = (const float*)d_in[3];
    const float* b_hh   = (const float*)d_in[4];
    const float* w_attn = (const float*)d_in[5];
    (void)in_sizes; (void)n_in; (void)out_size;

    float* out_w   = (float*)d_out;
    float* out_enc = out_w + (size_t)Bz * Tz * Dz;

    static int attr_done = 0;
    if (!attr_done) {
        cudaFuncSetAttribute(gemm_x, cudaFuncAttributeMaxDynamicSharedMemorySize, SMEM_SZ);
        cudaFuncSetAttribute(gemm_rec, cudaFuncAttributeMaxDynamicSharedMemorySize, SMEM_SZ);
        attr_done = 1;
    }

    init_kernel<<<(Bz * Hz + 255) / 256, 256>>>();
    attn_kernel<<<Bz, Dz>>>(x, w_attn);
    wx_kernel<<<(Bz * Tz * Dz / 4 + 255) / 256, 256>>>((const float4*)x, (float4*)out_w);
    prep_w_kernel<<<(G4 * Kz + 255) / 256, 256>>>(w_ih, w_hh, b_ih, b_hh);

    // G_x = WX @ W_ih'^T + bias   (M = 65536, N = 2048 interleaved, K = 512)
    gemm_x<<<dim3(G4 / 128, (Bz * Tz) / 128), 256, SMEM_SZ>>>(0);

    // persistent recurrence: all 64 steps in one launch
    gemm_rec<<<128, 256, SMEM_SZ>>>(out_enc);
}

// round 5
// speedup vs baseline: 4.2873x; 1.3906x over previous
#include <cuda_runtime.h>
#include <cuda_fp16.h>
#include <cstdint>
#include <cstddef>

#define Bz 1024
#define Tz 64
#define Dz 512
#define Hz 512
#define G4 2048
#define Kz 512

// ---------------- scratch (static __device__, allocation-free) ----------------
__device__ __align__(256) float g_attn[Bz * Dz];
__device__ __align__(256) float g_gx[(size_t)Bz * Tz * G4];     // 512 MB, interleaved cols (bias folded)
__device__ __align__(256) __half g_h[Bz * Hz];                  // fp16 h state
__device__ __align__(256) __half g_wx[(size_t)Bz * Tz * Dz];    // 64 MB fp16 wx
__device__ __align__(256) __half g_wih_hi[G4 * Dz];             // interleaved rows
__device__ __align__(256) __half g_wih_lo[G4 * Dz];
__device__ __align__(256) __half g_whh_hi[G4 * Hz];
__device__ __align__(256) __half g_whh_lo[G4 * Hz];
__device__ __align__(256) float g_bias[G4];                     // interleaved cols
__device__ unsigned g_bar[8];                                   // bm-group barriers

// ---------------- helpers ----------------
__device__ __forceinline__ uint32_t smem_u32(const void* p) {
    uint32_t a;
    asm("{ .reg .u64 t; cvta.to.shared.u64 t, %1; cvt.u32.u64 %0, t; }" : "=r"(a) : "l"(p));
    return a;
}
__device__ __forceinline__ unsigned ld_acq(const unsigned* p) {
    unsigned v;
    asm volatile("ld.acquire.gpu.global.u32 %0, [%1];" : "=r"(v) : "l"(p));
    return v;
}
__device__ __forceinline__ float sigm(float x) { return 1.f / (1.f + __expf(-x)); }
__device__ __forceinline__ float tanh_f(float x) { return 2.f / (1.f + __expf(-2.f * x)) - 1.f; }
__device__ __forceinline__ void split_h16(float v, __half& hi, __half& lo) {
    hi = __float2half_rn(v);
    lo = __float2half_rn(v - __half2float(hi));
}

#define LDSM4(r, addr)                                                      \
    asm volatile("ldmatrix.sync.aligned.m8n8.x4.shared.b16 {%0,%1,%2,%3}, [%4];" \
                 : "=r"((r)[0]), "=r"((r)[1]), "=r"((r)[2]), "=r"((r)[3])   \
                 : "r"(addr))

#define MMA(d, a, b0, b1)                                                   \
    asm volatile("mma.sync.aligned.m16n8k16.row.col.f32.f16.f16.f32 "       \
                 "{%0,%1,%2,%3}, {%4,%5,%6,%7}, {%8,%9}, {%0,%1,%2,%3};"    \
                 : "+f"((d)[0]), "+f"((d)[1]), "+f"((d)[2]), "+f"((d)[3])   \
                 : "r"((a)[0]), "r"((a)[1]), "r"((a)[2]), "r"((a)[3]),      \
                   "r"(b0), "r"(b1))

#define CP_ASYNC16(s, g) \
    asm volatile("cp.async.cg.shared.global [%0], [%1], 16;" :: "r"(s), "l"(g))
#define CP_COMMIT() asm volatile("cp.async.commit_group;" ::: "memory")
#define CP_WAIT(n)  asm volatile("cp.async.wait_group %0;" :: "n"(n) : "memory")

// smem: tiles of 128 rows x 32 halves, pitch 40 halves (80B)
#define MAT_BYTES 10240                    // 128 * 80
#define STAGE_BYTES (3 * MAT_BYTES)        // [A, Bhi, Blo] = 30720
#define GX_PITCH 132                       // floats
#define GX_BYTES (128 * GX_PITCH * 4)      // 67584
#define X_SMEM (2 * STAGE_BYTES)           // 61440
#define REC_SMEM (2 * STAGE_BYTES + GX_BYTES)  // 129024

// ---------------- init ----------------
__global__ void init_kernel() {
    int i = blockIdx.x * blockDim.x + threadIdx.x;
    if (i < Bz * Hz) g_h[i] = __float2half(0.f);
    if (i < 8) g_bar[i] = 0u;
}

// ---------------- attn = softmax_d( sum_t x[b,t,d] * w_x[t] ) ----------------
__global__ void attn_kernel(const float* __restrict__ x, const float* __restrict__ w_attn) {
    int b = blockIdx.x;
    int d = threadIdx.x;
    __shared__ float wxs[Tz];
    __shared__ float red[Dz];
    if (d < Tz) wxs[d] = w_attn[2 * Hz + d];
    __syncthreads();
    const float* xb = x + (size_t)b * Tz * Dz + d;
    float acc = 0.f;
#pragma unroll 8
    for (int t = 0; t < Tz; t++) acc = fmaf(xb[(size_t)t * Dz], wxs[t], acc);
    red[d] = acc;
    __syncthreads();
    for (int s = 256; s > 0; s >>= 1) {
        if (d < s) red[d] = fmaxf(red[d], red[d + s]);
        __syncthreads();
    }
    float m = red[0];
    __syncthreads();
    float e = __expf(acc - m);
    red[d] = e;
    __syncthreads();
    for (int s = 256; s > 0; s >>= 1) {
        if (d < s) red[d] += red[d + s];
        __syncthreads();
    }
    g_attn[b * Dz + d] = e / red[0];
}

// ---------------- wx = attn * x (fp32 output + single fp16 copy) ----------------
__global__ void wx_kernel(const float4* __restrict__ x4, float4* __restrict__ ow) {
    int i = blockIdx.x * blockDim.x + threadIdx.x;
    size_t e0 = (size_t)i * 4;
    int b = (int)(e0 >> 15);
    int d = (int)(e0 & (Dz - 1));
    float4 xv = x4[i];
    float4 a = *(const float4*)(g_attn + (size_t)b * Dz + d);
    float4 wv = make_float4(xv.x * a.x, xv.y * a.y, xv.z * a.z, xv.w * a.w);
    ow[i] = wv;
    *(__half2*)(g_wx + e0)     = __half2(__float2half_rn(wv.x), __float2half_rn(wv.y));
    *(__half2*)(g_wx + e0 + 2) = __half2(__float2half_rn(wv.z), __float2half_rn(wv.w));
}

// ---------------- weight prep: interleave rows + fp16 hi/lo split ----------------
// new row nr for (gate g, unit u): nr = (u/8)*32 + g*8 + (u%8)
__global__ void prep_w_kernel(const float* __restrict__ wih, const float* __restrict__ whh,
                              const float* __restrict__ bih, const float* __restrict__ bhh) {
    int i = blockIdx.x * blockDim.x + threadIdx.x;
    if (i < G4 * Kz) {
        int row = i >> 9;
        int k = i & 511;
        int g = row >> 9;
        int u = row & 511;
        int nr = ((u >> 3) << 5) + (g << 3) + (u & 7);
        __half hi, lo;
        split_h16(wih[i], hi, lo);
        g_wih_hi[nr * 512 + k] = hi;
        g_wih_lo[nr * 512 + k] = lo;
        split_h16(whh[i], hi, lo);
        g_whh_hi[nr * 512 + k] = hi;
        g_whh_lo[nr * 512 + k] = lo;
        if (i < G4) {
            int gg = i >> 9, uu = i & 511;
            int nb = ((uu >> 3) << 5) + (gg << 3) + (uu & 7);
            g_bias[nb] = bih[i] + bhh[i];
        }
    }
}

// ---------------- shared mainloop: 128x128 fp16 2-pass tile into acc ----------------
template <typename PF>
__device__ __forceinline__ void mma_mainloop(char* smem, int lane, int wm, int wn,
                                             float (&acc)[4][4][4], PF&& prefetch) {
#pragma unroll
    for (int a = 0; a < 4; a++)
#pragma unroll
        for (int b = 0; b < 4; b++)
#pragma unroll
            for (int cidx = 0; cidx < 4; cidx++) acc[a][b][cidx] = 0.f;

    for (int kt = 0; kt < 16; kt++) {
        if (kt + 1 < 16) {
            prefetch(kt + 1, (kt + 1) & 1);
            CP_COMMIT();
            CP_WAIT(1);
        } else {
            CP_WAIT(0);
        }
        __syncthreads();

        char* sbase = smem + (kt & 1) * STAGE_BYTES;
#pragma unroll
        for (int kk = 0; kk < 2; kk++) {
            uint32_t av[4][4], bhi[2][4], blo[2][4];
            uint32_t a_off = (uint32_t)((wm * 64 + (lane & 15)) * 80 + (lane >> 4) * 16 + kk * 32);
#pragma unroll
            for (int mi = 0; mi < 4; mi++)
                LDSM4(av[mi], smem_u32(sbase + 0 * MAT_BYTES + a_off + mi * 16 * 80));
            uint32_t b_off = (uint32_t)((wn * 32 + (lane >> 4) * 8 + (lane & 7)) * 80 +
                                        ((lane >> 3) & 1) * 16 + kk * 32);
#pragma unroll
            for (int p = 0; p < 2; p++) {
                LDSM4(bhi[p], smem_u32(sbase + 1 * MAT_BYTES + b_off + p * 16 * 80));
                LDSM4(blo[p], smem_u32(sbase + 2 * MAT_BYTES + b_off + p * 16 * 80));
            }
#pragma unroll
            for (int mi = 0; mi < 4; mi++)
#pragma unroll
                for (int ni = 0; ni < 4; ni++)
                    MMA(acc[mi][ni], av[mi], bhi[ni >> 1][(ni & 1) * 2], bhi[ni >> 1][(ni & 1) * 2 + 1]);
#pragma unroll
            for (int mi = 0; mi < 4; mi++)
#pragma unroll
                for (int ni = 0; ni < 4; ni++)
                    MMA(acc[mi][ni], av[mi], blo[ni >> 1][(ni & 1) * 2], blo[ni >> 1][(ni & 1) * 2 + 1]);
        }
        __syncthreads();
    }
}

// ---------------- x-GEMM: G_x = WX @ W_ih'^T + bias ----------------
__global__ void __launch_bounds__(256, 2)
gemm_x(int dummy) {
    extern __shared__ char smem[];
    const int tid = threadIdx.x;
    const int lane = tid & 31, wid = tid >> 5;
    const int wm = wid >> 2, wn = wid & 3;
    const int bn = blockIdx.x, bm = blockIdx.y;

    const __half* A   = g_wx + (size_t)bm * 128 * Kz;
    const __half* Bh  = g_wih_hi + (size_t)bn * 128 * Kz;
    const __half* Bl  = g_wih_lo + (size_t)bn * 128 * Kz;
    const __half* srcs[3] = {A, Bh, Bl};

    auto prefetch = [&](int kt, int stage) {
        int k0 = kt * 32;
        char* sbase = smem + stage * STAGE_BYTES;
#pragma unroll
        for (int m = 0; m < 3; m++) {
#pragma unroll
            for (int j = 0; j < 2; j++) {
                int ci = tid * 2 + j;
                int row = ci >> 2, c16 = ci & 3;
                const void* g = srcs[m] + (size_t)row * Kz + k0 + c16 * 8;
                uint32_t s = smem_u32(sbase + m * MAT_BYTES + row * 80 + c16 * 16);
                CP_ASYNC16(s, g);
            }
        }
    };

    prefetch(0, 0);
    CP_COMMIT();

    float acc[4][4][4];
    mma_mainloop(smem, lane, wm, wn, acc, prefetch);

    const int r0 = bm * 128 + wm * 64 + (lane >> 2);
#pragma unroll
    for (int ni = 0; ni < 4; ni++) {
        int c = bn * 128 + wn * 32 + ni * 8 + (lane & 3) * 2;
        float2 bi = *(const float2*)(g_bias + c);
#pragma unroll
        for (int mi = 0; mi < 4; mi++) {
            int r = r0 + mi * 16;
            *(float2*)(g_gx + (size_t)r * G4 + c) =
                make_float2(acc[mi][ni][0] + bi.x, acc[mi][ni][1] + bi.y);
            *(float2*)(g_gx + (size_t)(r + 8) * G4 + c) =
                make_float2(acc[mi][ni][2] + bi.x, acc[mi][ni][3] + bi.y);
        }
    }
}

// ---------------- persistent recurrence: 64 steps, c in registers, gx staged ----------------
__global__ void __launch_bounds__(256)
gemm_rec(float* __restrict__ out_enc) {
    extern __shared__ char smem[];
    char* gxbuf = smem + 2 * STAGE_BYTES;
    const int tid = threadIdx.x;
    const int lane = tid & 31, wid = tid >> 5;
    const int wm = wid >> 2, wn = wid & 3;
    const int bn = blockIdx.x & 15, bm = blockIdx.x >> 4;

    const __half* A  = g_h + (size_t)bm * 128 * Kz;
    const __half* Bh = g_whh_hi + (size_t)bn * 128 * Kz;
    const __half* Bl = g_whh_lo + (size_t)bn * 128 * Kz;
    const __half* srcs[3] = {A, Bh, Bl};

    auto prefetch = [&](int kt, int stage) {
        int k0 = kt * 32;
        char* sbase = smem + stage * STAGE_BYTES;
#pragma unroll
        for (int m = 0; m < 3; m++) {
#pragma unroll
            for (int j = 0; j < 2; j++) {
                int ci = tid * 2 + j;
                int row = ci >> 2, c16 = ci & 3;
                const void* g = srcs[m] + (size_t)row * Kz + k0 + c16 * 8;
                uint32_t s = smem_u32(sbase + m * MAT_BYTES + row * 80 + c16 * 16);
                CP_ASYNC16(s, g);
            }
        }
    };

    const int r0 = bm * 128 + wm * 64 + (lane >> 2);
    const int U = (bn * 4 + wn) * 8 + (lane & 3) * 2;

    float c_reg[4][2][2];
#pragma unroll
    for (int mi = 0; mi < 4; mi++)
#pragma unroll
        for (int h = 0; h < 2; h++) { c_reg[mi][h][0] = 0.f; c_reg[mi][h][1] = 0.f; }

    for (int t = 0; t < Tz; t++) {
        // stage 0 + this step's gx slice (128 rows x 128 floats) in one cp.async group
        prefetch(0, 0);
        {
            const float* gsrc = g_gx + (size_t)bm * 128 * Tz * G4 + (size_t)t * G4 + bn * 128;
#pragma unroll
            for (int q = 0; q < 16; q++) {
                int ci = tid + q * 256;
                int row = ci >> 5, cc = ci & 31;
                const void* g = gsrc + (size_t)row * Tz * G4 + cc * 4;
                uint32_t s = smem_u32(gxbuf + row * (GX_PITCH * 4) + cc * 16);
                CP_ASYNC16(s, g);
            }
        }
        CP_COMMIT();

        float acc[4][4][4];
        mma_mainloop(smem, lane, wm, wn, acc, prefetch);

        // ---- fused LSTM epilogue (gx from smem, c in registers) ----
#pragma unroll
        for (int mi = 0; mi < 4; mi++) {
#pragma unroll
            for (int half = 0; half < 2; half++) {
                int mloc = wm * 64 + mi * 16 + half * 8 + (lane >> 2);
                int m = bm * 128 + mloc;
                int j0 = half * 2;
                const float* gxr = (const float*)(gxbuf + mloc * (GX_PITCH * 4)) +
                                   wn * 32 + (lane & 3) * 2;
                float2 gI = *(const float2*)(gxr + 0);
                float2 gF = *(const float2*)(gxr + 8);
                float2 gG = *(const float2*)(gxr + 16);
                float2 gO = *(const float2*)(gxr + 24);
                float gi0 = acc[mi][0][j0] + gI.x, gi1 = acc[mi][0][j0 + 1] + gI.y;
                float gf0 = acc[mi][1][j0] + gF.x, gf1 = acc[mi][1][j0 + 1] + gF.y;
                float gg0 = acc[mi][2][j0] + gG.x, gg1 = acc[mi][2][j0 + 1] + gG.y;
                float go0 = acc[mi][3][j0] + gO.x, go1 = acc[mi][3][j0 + 1] + gO.y;
                float c20 = sigm(gf0) * c_reg[mi][half][0] + sigm(gi0) * tanh_f(gg0);
                float c21 = sigm(gf1) * c_reg[mi][half][1] + sigm(gi1) * tanh_f(gg1);
                c_reg[mi][half][0] = c20;
                c_reg[mi][half][1] = c21;
                float h20 = sigm(go0) * tanh_f(c20);
                float h21 = sigm(go1) * tanh_f(c21);
                *(float2*)(out_enc + ((size_t)m * Tz + t) * Hz + U) = make_float2(h20, h21);
                *(__half2*)(g_h + (size_t)m * Hz + U) =
                    __half2(__float2half_rn(h20), __float2half_rn(h21));
            }
        }

        // ---- bm-group barrier (16 CTAs share h rows of bm) ----
        if (t + 1 < Tz) {
            __threadfence();
            __syncthreads();
            if (tid == 0) {
                atomicAdd(&g_bar[bm], 1u);
                unsigned target = 16u * (unsigned)(t + 1);
                while (ld_acq(&g_bar[bm]) < target) { }
            }
            __syncthreads();
        }
    }
}

// ---------------- launch ----------------
extern "C" void kernel_launch(void* const* d_in, const int* in_sizes, int n_in,
                              void* d_out, int out_size) {
    const float* x      = (const float*)d_in[0];
    const float* w_ih   = (const float*)d_in[1];
    const float* w_hh   = (const float*)d_in[2];
    const float* b_ih   = (const float*)d_in[3];
    const float* b_hh   = (const float*)d_in[4];
    const float* w_attn = (const float*)d_in[5];
    (void)in_sizes; (void)n_in; (void)out_size;

    float* out_w   = (float*)d_out;
    float* out_enc = out_w + (size_t)Bz * Tz * Dz;

    static int attr_done = 0;
    if (!attr_done) {
        cudaFuncSetAttribute(gemm_x, cudaFuncAttributeMaxDynamicSharedMemorySize, X_SMEM);
        cudaFuncSetAttribute(gemm_rec, cudaFuncAttributeMaxDynamicSharedMemorySize, REC_SMEM);
        attr_done = 1;
    }

    init_kernel<<<(Bz * Hz + 255) / 256, 256>>>();
    attn_kernel<<<Bz, Dz>>>(x, w_attn);
    wx_kernel<<<(Bz * Tz * Dz / 4 + 255) / 256, 256>>>((const float4*)x, (float4*)out_w);
    prep_w_kernel<<<(G4 * Kz + 255) / 256, 256>>>(w_ih, w_hh, b_ih, b_hh);

    // G_x = WX @ W_ih'^T + bias   (M = 65536, N = 2048 interleaved, K = 512)
    gemm_x<<<dim3(G4 / 128, (Bz * Tz) / 128), 256, X_SMEM>>>(0);

    // persistent recurrence: all 64 steps in one launch
    gemm_rec<<<128, 256, REC_SMEM>>>(out_enc);
}

// round 6
// speedup vs baseline: 6.9320x; 1.6169x over previous
#include <cuda_runtime.h>
#include <cuda_fp16.h>
#include <cstdint>
#include <cstddef>

#define Bz 1024
#define Tz 64
#define Dz 512
#define Hz 512
#define G4 2048
#define Kz 512

// ---------------- scratch (static __device__, allocation-free) ----------------
__device__ __align__(256) __half g_gx16[(size_t)Bz * Tz * G4];  // 256 MB x-gates (fp16, bias folded)
__device__ __align__(256) __half g_h[Bz * Hz];                  // fp16 h state
__device__ __align__(256) __half g_wx[(size_t)Bz * Tz * Dz];    // 64 MB fp16 wx
__device__ __align__(256) __half g_wih[G4 * Dz];                // interleaved rows, fp16
__device__ __align__(256) __half g_whh[G4 * Hz];
__device__ __align__(256) float g_bias[G4];                     // interleaved cols
__device__ unsigned g_bar[8];                                   // bm-group barriers

// ---------------- helpers ----------------
__device__ __forceinline__ uint32_t smem_u32(const void* p) {
    uint32_t a;
    asm("{ .reg .u64 t; cvta.to.shared.u64 t, %1; cvt.u32.u64 %0, t; }" : "=r"(a) : "l"(p));
    return a;
}
__device__ __forceinline__ unsigned ld_acq(const unsigned* p) {
    unsigned v;
    asm volatile("ld.acquire.gpu.global.u32 %0, [%1];" : "=r"(v) : "l"(p));
    return v;
}
__device__ __forceinline__ float sigm(float x) { return 1.f / (1.f + __expf(-x)); }
__device__ __forceinline__ float tanh_f(float x) { return 2.f / (1.f + __expf(-2.f * x)) - 1.f; }

#define LDSM4(r, addr)                                                      \
    asm volatile("ldmatrix.sync.aligned.m8n8.x4.shared.b16 {%0,%1,%2,%3}, [%4];" \
                 : "=r"((r)[0]), "=r"((r)[1]), "=r"((r)[2]), "=r"((r)[3])   \
                 : "r"(addr))

#define MMA(d, a, b0, b1)                                                   \
    asm volatile("mma.sync.aligned.m16n8k16.row.col.f32.f16.f16.f32 "       \
                 "{%0,%1,%2,%3}, {%4,%5,%6,%7}, {%8,%9}, {%0,%1,%2,%3};"    \
                 : "+f"((d)[0]), "+f"((d)[1]), "+f"((d)[2]), "+f"((d)[3])   \
                 : "r"((a)[0]), "r"((a)[1]), "r"((a)[2]), "r"((a)[3]),      \
                   "r"(b0), "r"(b1))

#define CP_ASYNC16(s, g) \
    asm volatile("cp.async.cg.shared.global [%0], [%1], 16;" :: "r"(s), "l"(g))
#define CP_COMMIT() asm volatile("cp.async.commit_group;" ::: "memory")
#define CP_WAIT(n)  asm volatile("cp.async.wait_group %0;" :: "n"(n) : "memory")

// ---- gemm_x smem: stages of [A, B], each 128 rows x 32 halves, pitch 80 B ----
#define MAT_BYTES 10240
#define STAGE_X (2 * MAT_BYTES)            // 20480
#define X_SMEM (2 * STAGE_X)               // 40960

// ---- gemm_rec smem: B resident + A double-buffer + gx slice ----
#define BRP 1040                           // B resident pitch (bytes): 512 halves + 16 pad
#define B_RES_BYTES (128 * BRP)            // 133120
#define RA_OFF B_RES_BYTES
#define RA_STAGE 10240
#define RGX_OFF (RA_OFF + 2 * RA_STAGE)    // 153600
#define RGXP 272                           // gx pitch (bytes): 128 halves + 16 pad
#define REC_SMEM (RGX_OFF + 128 * RGXP)    // 188416

// ---------------- init ----------------
__global__ void init_kernel() {
    int i = blockIdx.x * blockDim.x + threadIdx.x;
    if (i < Bz * Hz) g_h[i] = __float2half(0.f);
    if (i < 8) g_bar[i] = 0u;
}

// ---------------- fused attn + wx ----------------
__global__ void __launch_bounds__(512)
attn_wx_kernel(const float* __restrict__ x, const float* __restrict__ w_attn,
               float* __restrict__ out_w) {
    int b = blockIdx.x;
    int d = threadIdx.x;
    __shared__ float wxs[Tz];
    __shared__ float red[Dz];
    if (d < Tz) wxs[d] = w_attn[2 * Hz + d];
    __syncthreads();
    const float* xb = x + (size_t)b * Tz * Dz + d;
    float acc = 0.f;
#pragma unroll 8
    for (int t = 0; t < Tz; t++) acc = fmaf(xb[(size_t)t * Dz], wxs[t], acc);
    red[d] = acc;
    __syncthreads();
    for (int s = 256; s > 0; s >>= 1) {
        if (d < s) red[d] = fmaxf(red[d], red[d + s]);
        __syncthreads();
    }
    float m = red[0];
    __syncthreads();
    float e = __expf(acc - m);
    red[d] = e;
    __syncthreads();
    for (int s = 256; s > 0; s >>= 1) {
        if (d < s) red[d] += red[d + s];
        __syncthreads();
    }
    float a = e / red[0];
    // second pass: wx (x re-read hits L2)
    float* owb = out_w + (size_t)b * Tz * Dz + d;
    __half* wxb = g_wx + (size_t)b * Tz * Dz + d;
#pragma unroll 4
    for (int t = 0; t < Tz; t++) {
        float v = xb[(size_t)t * Dz] * a;
        owb[(size_t)t * Dz] = v;
        wxb[(size_t)t * Dz] = __float2half_rn(v);
    }
}

// ---------------- weight prep: interleave rows, fp16 ----------------
// nr for (gate g, unit u): nr = (u/8)*32 + g*8 + (u%8)
__global__ void prep_w_kernel(const float* __restrict__ wih, const float* __restrict__ whh,
                              const float* __restrict__ bih, const float* __restrict__ bhh) {
    int i = blockIdx.x * blockDim.x + threadIdx.x;
    if (i < G4 * Kz) {
        int row = i >> 9;
        int k = i & 511;
        int g = row >> 9;
        int u = row & 511;
        int nr = ((u >> 3) << 5) + (g << 3) + (u & 7);
        g_wih[nr * 512 + k] = __float2half_rn(wih[i]);
        g_whh[nr * 512 + k] = __float2half_rn(whh[i]);
        if (i < G4) {
            int gg = i >> 9, uu = i & 511;
            int nb = ((uu >> 3) << 5) + (gg << 3) + (uu & 7);
            g_bias[nb] = bih[i] + bhh[i];
        }
    }
}

// ---------------- x-GEMM: G_x = WX @ W_ih'^T + bias (single-pass fp16) ----------------
__global__ void __launch_bounds__(256, 2)
gemm_x(int dummy) {
    extern __shared__ char smem[];
    const int tid = threadIdx.x;
    const int lane = tid & 31, wid = tid >> 5;
    const int wm = wid >> 2, wn = wid & 3;
    const int bn = blockIdx.x, bm = blockIdx.y;

    const __half* A = g_wx + (size_t)bm * 128 * Kz;
    const __half* B = g_wih + (size_t)bn * 128 * Kz;
    const __half* srcs[2] = {A, B};

    auto prefetch = [&](int kt, int stage) {
        int k0 = kt * 32;
        char* sbase = smem + stage * STAGE_X;
#pragma unroll
        for (int m = 0; m < 2; m++) {
#pragma unroll
            for (int j = 0; j < 2; j++) {
                int ci = tid * 2 + j;
                int row = ci >> 2, c16 = ci & 3;
                const void* g = srcs[m] + (size_t)row * Kz + k0 + c16 * 8;
                uint32_t s = smem_u32(sbase + m * MAT_BYTES + row * 80 + c16 * 16);
                CP_ASYNC16(s, g);
            }
        }
    };

    float acc[4][4][4];
#pragma unroll
    for (int a = 0; a < 4; a++)
#pragma unroll
        for (int b = 0; b < 4; b++)
#pragma unroll
            for (int c = 0; c < 4; c++) acc[a][b][c] = 0.f;

    prefetch(0, 0);
    CP_COMMIT();

    for (int kt = 0; kt < 16; kt++) {
        if (kt + 1 < 16) {
            prefetch(kt + 1, (kt + 1) & 1);
            CP_COMMIT();
            CP_WAIT(1);
        } else {
            CP_WAIT(0);
        }
        __syncthreads();
        char* sbase = smem + (kt & 1) * STAGE_X;
#pragma unroll
        for (int kk = 0; kk < 2; kk++) {
            uint32_t av[4][4], bq[2][4];
            uint32_t a_off = (uint32_t)((wm * 64 + (lane & 15)) * 80 + (lane >> 4) * 16 + kk * 32);
#pragma unroll
            for (int mi = 0; mi < 4; mi++)
                LDSM4(av[mi], smem_u32(sbase + a_off + mi * 16 * 80));
            uint32_t b_off = (uint32_t)((wn * 32 + (lane >> 4) * 8 + (lane & 7)) * 80 +
                                        ((lane >> 3) & 1) * 16 + kk * 32);
#pragma unroll
            for (int p = 0; p < 2; p++)
                LDSM4(bq[p], smem_u32(sbase + MAT_BYTES + b_off + p * 16 * 80));
#pragma unroll
            for (int mi = 0; mi < 4; mi++)
#pragma unroll
                for (int ni = 0; ni < 4; ni++)
                    MMA(acc[mi][ni], av[mi], bq[ni >> 1][(ni & 1) * 2], bq[ni >> 1][(ni & 1) * 2 + 1]);
        }
        __syncthreads();
    }

    const int r0 = bm * 128 + wm * 64 + (lane >> 2);
#pragma unroll
    for (int ni = 0; ni < 4; ni++) {
        int c = bn * 128 + wn * 32 + ni * 8 + (lane & 3) * 2;
        float2 bi = *(const float2*)(g_bias + c);
#pragma unroll
        for (int mi = 0; mi < 4; mi++) {
            int r = r0 + mi * 16;
            *(__half2*)(g_gx16 + (size_t)r * G4 + c) =
                __half2(__float2half_rn(acc[mi][ni][0] + bi.x), __float2half_rn(acc[mi][ni][1] + bi.y));
            *(__half2*)(g_gx16 + (size_t)(r + 8) * G4 + c) =
                __half2(__float2half_rn(acc[mi][ni][2] + bi.x), __float2half_rn(acc[mi][ni][3] + bi.y));
        }
    }
}

// ---------------- persistent recurrence: W_hh resident, A streamed, gx staged ----------------
__global__ void __launch_bounds__(256)
gemm_rec(float* __restrict__ out_enc) {
    extern __shared__ char smem[];
    const int tid = threadIdx.x;
    const int lane = tid & 31, wid = tid >> 5;
    const int wm = wid >> 2, wn = wid & 3;
    const int bn = blockIdx.x & 15, bm = blockIdx.x >> 4;

    // ---- load W_hh tile resident (128 gate-cols x 512 k, fp16) ----
    for (int i = tid; i < 8192; i += 256) {
        int row = i >> 6, c = i & 63;
        CP_ASYNC16(smem_u32(smem + row * BRP + c * 16),
                   g_whh + (size_t)(bn * 128 + row) * 512 + c * 8);
    }
    CP_COMMIT();
    CP_WAIT(0);
    __syncthreads();

    const __half* A = g_h + (size_t)bm * 128 * Kz;
    auto prefA = [&](int kt, int stage) {
        int k0 = kt * 32;
        char* sb = smem + RA_OFF + stage * RA_STAGE;
#pragma unroll
        for (int j = 0; j < 2; j++) {
            int ci = tid * 2 + j;
            int row = ci >> 2, c16 = ci & 3;
            CP_ASYNC16(smem_u32(sb + row * 80 + c16 * 16),
                       A + (size_t)row * Kz + k0 + c16 * 8);
        }
    };

    const int U = (bn * 4 + wn) * 8 + (lane & 3) * 2;

    float c_reg[4][2][2];
#pragma unroll
    for (int mi = 0; mi < 4; mi++)
#pragma unroll
        for (int h = 0; h < 2; h++) { c_reg[mi][h][0] = 0.f; c_reg[mi][h][1] = 0.f; }

    for (int t = 0; t < Tz; t++) {
        // group 0: A chunk 0 + this step's gx slice (128 x 128 fp16)
        prefA(0, 0);
        {
#pragma unroll
            for (int q = 0; q < 8; q++) {
                int ci = tid + q * 256;          // 0..2047
                int row = ci >> 4, c = ci & 15;
                const void* g = g_gx16 + ((size_t)(bm * 128 + row) * Tz + t) * G4 + bn * 128 + c * 8;
                CP_ASYNC16(smem_u32(smem + RGX_OFF + row * RGXP + c * 16), g);
            }
        }
        CP_COMMIT();

        float acc[4][4][4];
#pragma unroll
        for (int a = 0; a < 4; a++)
#pragma unroll
            for (int b = 0; b < 4; b++)
#pragma unroll
                for (int c = 0; c < 4; c++) acc[a][b][c] = 0.f;

        for (int kt = 0; kt < 16; kt++) {
            if (kt + 1 < 16) {
                prefA(kt + 1, (kt + 1) & 1);
                CP_COMMIT();
                CP_WAIT(1);
            } else {
                CP_WAIT(0);
            }
            __syncthreads();
            char* sa = smem + RA_OFF + (kt & 1) * RA_STAGE;
#pragma unroll
            for (int kk = 0; kk < 2; kk++) {
                uint32_t av[4][4], bq[2][4];
                uint32_t a_off = (uint32_t)((wm * 64 + (lane & 15)) * 80 + (lane >> 4) * 16 + kk * 32);
#pragma unroll
                for (int mi = 0; mi < 4; mi++)
                    LDSM4(av[mi], smem_u32(sa + a_off + mi * 16 * 80));
                uint32_t b_off = (uint32_t)((wn * 32 + (lane >> 4) * 8 + (lane & 7)) * BRP +
                                            kt * 64 + kk * 32 + ((lane >> 3) & 1) * 16);
#pragma unroll
                for (int p = 0; p < 2; p++)
                    LDSM4(bq[p], smem_u32(smem + b_off + p * 16 * BRP));
#pragma unroll
                for (int mi = 0; mi < 4; mi++)
#pragma unroll
                    for (int ni = 0; ni < 4; ni++)
                        MMA(acc[mi][ni], av[mi], bq[ni >> 1][(ni & 1) * 2], bq[ni >> 1][(ni & 1) * 2 + 1]);
            }
            __syncthreads();
        }

        // ---- fused LSTM epilogue (gx from smem, c in registers) ----
#pragma unroll
        for (int mi = 0; mi < 4; mi++) {
#pragma unroll
            for (int half = 0; half < 2; half++) {
                int mloc = wm * 64 + mi * 16 + half * 8 + (lane >> 2);
                int m = bm * 128 + mloc;
                int j0 = half * 2;
                const __half* gxr = (const __half*)(smem + RGX_OFF + mloc * RGXP) +
                                    wn * 32 + (lane & 3) * 2;
                float2 gI = __half22float2(*(const __half2*)(gxr + 0));
                float2 gF = __half22float2(*(const __half2*)(gxr + 8));
                float2 gG = __half22float2(*(const __half2*)(gxr + 16));
                float2 gO = __half22float2(*(const __half2*)(gxr + 24));
                float gi0 = acc[mi][0][j0] + gI.x, gi1 = acc[mi][0][j0 + 1] + gI.y;
                float gf0 = acc[mi][1][j0] + gF.x, gf1 = acc[mi][1][j0 + 1] + gF.y;
                float gg0 = acc[mi][2][j0] + gG.x, gg1 = acc[mi][2][j0 + 1] + gG.y;
                float go0 = acc[mi][3][j0] + gO.x, go1 = acc[mi][3][j0 + 1] + gO.y;
                float c20 = sigm(gf0) * c_reg[mi][half][0] + sigm(gi0) * tanh_f(gg0);
                float c21 = sigm(gf1) * c_reg[mi][half][1] + sigm(gi1) * tanh_f(gg1);
                c_reg[mi][half][0] = c20;
                c_reg[mi][half][1] = c21;
                float h20 = sigm(go0) * tanh_f(c20);
                float h21 = sigm(go1) * tanh_f(c21);
                *(float2*)(out_enc + ((size_t)m * Tz + t) * Hz + U) = make_float2(h20, h21);
                *(__half2*)(g_h + (size_t)m * Hz + U) =
                    __half2(__float2half_rn(h20), __float2half_rn(h21));
            }
        }

        // ---- bm-group barrier (16 CTAs share h rows of bm) ----
        if (t + 1 < Tz) {
            __threadfence();
            __syncthreads();
            if (tid == 0) {
                atomicAdd(&g_bar[bm], 1u);
                unsigned target = 16u * (unsigned)(t + 1);
                while (ld_acq(&g_bar[bm]) < target) { }
            }
            __syncthreads();
        }
    }
}

// ---------------- launch ----------------
extern "C" void kernel_launch(void* const* d_in, const int* in_sizes, int n_in,
                              void* d_out, int out_size) {
    const float* x      = (const float*)d_in[0];
    const float* w_ih   = (const float*)d_in[1];
    const float* w_hh   = (const float*)d_in[2];
    const float* b_ih   = (const float*)d_in[3];
    const float* b_hh   = (const float*)d_in[4];
    const float* w_attn = (const float*)d_in[5];
    (void)in_sizes; (void)n_in; (void)out_size;

    float* out_w   = (float*)d_out;
    float* out_enc = out_w + (size_t)Bz * Tz * Dz;

    static int attr_done = 0;
    if (!attr_done) {
        cudaFuncSetAttribute(gemm_x, cudaFuncAttributeMaxDynamicSharedMemorySize, X_SMEM);
        cudaFuncSetAttribute(gemm_rec, cudaFuncAttributeMaxDynamicSharedMemorySize, REC_SMEM);
        attr_done = 1;
    }

    init_kernel<<<(Bz * Hz + 255) / 256, 256>>>();
    attn_wx_kernel<<<Bz, Dz>>>(x, w_attn, out_w);
    prep_w_kernel<<<(G4 * Kz + 255) / 256, 256>>>(w_ih, w_hh, b_ih, b_hh);

    // G_x = WX @ W_ih'^T + bias   (M = 65536, N = 2048 interleaved, K = 512)
    gemm_x<<<dim3(G4 / 128, (Bz * Tz) / 128), 256, X_SMEM>>>(0);

    // persistent recurrence: all 64 steps in one launch
    gemm_rec<<<128, 256, REC_SMEM>>>(out_enc);
}

// round 8
// speedup vs baseline: 8.5217x; 1.2293x over previous
#include <cuda_runtime.h>
#include <cuda_fp16.h>
#include <cstdint>
#include <cstddef>

#define Bz 1024
#define Tz 64
#define Dz 512
#define Hz 512
#define G4 2048
#define Kz 512

// ---------------- scratch (static __device__, allocation-free) ----------------
__device__ __align__(256) __half g_gx16[(size_t)Bz * Tz * G4];  // 256 MB x-gates (fp16, bias folded)
__device__ __align__(256) __half g_h2[2 * Bz * Hz];             // double-buffered fp16 h
__device__ __align__(256) __half g_wx[(size_t)Bz * Tz * Dz];    // 64 MB fp16 wx
__device__ __align__(256) __half g_wih[G4 * Dz];                // interleaved rows, fp16
__device__ __align__(256) __half g_whh[G4 * Hz];
__device__ __align__(256) float g_bias[G4];                     // interleaved cols
__device__ unsigned g_flag[128];                                // per-(bm,bn) producer flags

// ---------------- helpers ----------------
__device__ __forceinline__ uint32_t smem_u32(const void* p) {
    uint32_t a;
    asm("{ .reg .u64 t; cvta.to.shared.u64 t, %1; cvt.u32.u64 %0, t; }" : "=r"(a) : "l"(p));
    return a;
}
__device__ __forceinline__ unsigned ld_acq(const unsigned* p) {
    unsigned v;
    asm volatile("ld.acquire.gpu.global.u32 %0, [%1];" : "=r"(v) : "l"(p));
    return v;
}
__device__ __forceinline__ float frcp(float x) {
    float r;
    asm("rcp.approx.f32 %0, %1;" : "=f"(r) : "f"(x));
    return r;
}
__device__ __forceinline__ float sigm(float x) { return frcp(1.f + __expf(-x)); }
__device__ __forceinline__ float tanh_f(float x) { return fmaf(2.f, frcp(1.f + __expf(-2.f * x)), -1.f); }
__device__ __forceinline__ void st_cs_u32(void* p, uint32_t v) {
    asm volatile("st.global.cs.u32 [%0], %1;" :: "l"(p), "r"(v));
}
__device__ __forceinline__ uint32_t pack_h2(float a, float b) {
    __half2 h = __floats2half2_rn(a, b);
    return *(uint32_t*)&h;
}

#define LDSM4(r, addr)                                                      \
    asm volatile("ldmatrix.sync.aligned.m8n8.x4.shared.b16 {%0,%1,%2,%3}, [%4];" \
                 : "=r"((r)[0]), "=r"((r)[1]), "=r"((r)[2]), "=r"((r)[3])   \
                 : "r"(addr))

#define MMA(d, a, b0, b1)                                                   \
    asm volatile("mma.sync.aligned.m16n8k16.row.col.f32.f16.f16.f32 "       \
                 "{%0,%1,%2,%3}, {%4,%5,%6,%7}, {%8,%9}, {%0,%1,%2,%3};"    \
                 : "+f"((d)[0]), "+f"((d)[1]), "+f"((d)[2]), "+f"((d)[3])   \
                 : "r"((a)[0]), "r"((a)[1]), "r"((a)[2]), "r"((a)[3]),      \
                   "r"(b0), "r"(b1))

#define CP_ASYNC16(s, g) \
    asm volatile("cp.async.cg.shared.global [%0], [%1], 16;" :: "r"(s), "l"(g))
#define CP_COMMIT() asm volatile("cp.async.commit_group;" ::: "memory")
#define CP_WAIT(n)  asm volatile("cp.async.wait_group %0;" :: "n"(n) : "memory")

// ---- gemm_x smem: 3 stages of [A, B], each 128 rows x 32 halves, pitch 80 B ----
#define MAT_BYTES 10240
#define X_STAGE (2 * MAT_BYTES)            // 20480
#define X_SMEM (3 * X_STAGE)               // 61440

// ---- gemm_rec smem layout ----
#define BRP 1040                           // B resident pitch (512 halves + 16B pad)
#define RA_OFF (128 * BRP)                 // 133120
#define RA_STAGE 8192                      // A: 128 rows x 64B (swizzled)
#define RGX_OFF (RA_OFF + 3 * RA_STAGE)    // 157696
#define RGXP 272                           // gx pitch: 128 halves + 16B pad
#define RGX_BUF (128 * RGXP)               // 34816
#define REC_SMEM (RGX_OFF + 2 * RGX_BUF)   // 227328

// ---------------- init ----------------
__global__ void init_kernel() {
    int i = blockIdx.x * blockDim.x + threadIdx.x;
    if (i < Bz * Hz) g_h2[i] = __float2half(0.f);   // buffer 0 = h(t=0)
    if (i < 128) g_flag[i] = 0u;
}

// ---------------- fused attn + wx ----------------
__global__ void __launch_bounds__(512)
attn_wx_kernel(const float* __restrict__ x, const float* __restrict__ w_attn,
               float* __restrict__ out_w) {
    int b = blockIdx.x;
    int d = threadIdx.x;
    __shared__ float wxs[Tz];
    __shared__ float red[Dz];
    if (d < Tz) wxs[d] = w_attn[2 * Hz + d];
    __syncthreads();
    const float* xb = x + (size_t)b * Tz * Dz + d;
    float acc = 0.f;
#pragma unroll 8
    for (int t = 0; t < Tz; t++) acc = fmaf(xb[(size_t)t * Dz], wxs[t], acc);
    red[d] = acc;
    __syncthreads();
    for (int s = 256; s > 0; s >>= 1) {
        if (d < s) red[d] = fmaxf(red[d], red[d + s]);
        __syncthreads();
    }
    float m = red[0];
    __syncthreads();
    float e = __expf(acc - m);
    red[d] = e;
    __syncthreads();
    for (int s = 256; s > 0; s >>= 1) {
        if (d < s) red[d] += red[d + s];
        __syncthreads();
    }
    float a = e / red[0];
    float* owb = out_w + (size_t)b * Tz * Dz + d;
    __half* wxb = g_wx + (size_t)b * Tz * Dz + d;
#pragma unroll 4
    for (int t = 0; t < Tz; t++) {
        float v = xb[(size_t)t * Dz] * a;
        owb[(size_t)t * Dz] = v;
        wxb[(size_t)t * Dz] = __float2half_rn(v);
    }
}

// ---------------- weight prep: interleave rows, fp16 ----------------
// nr for (gate g, unit u): nr = (u/8)*32 + g*8 + (u%8)
__global__ void prep_w_kernel(const float* __restrict__ wih, const float* __restrict__ whh,
                              const float* __restrict__ bih, const float* __restrict__ bhh) {
    int i = blockIdx.x * blockDim.x + threadIdx.x;
    if (i < G4 * Kz) {
        int row = i >> 9;
        int k = i & 511;
        int g = row >> 9;
        int u = row & 511;
        int nr = ((u >> 3) << 5) + (g << 3) + (u & 7);
        g_wih[nr * 512 + k] = __float2half_rn(wih[i]);
        g_whh[nr * 512 + k] = __float2half_rn(whh[i]);
        if (i < G4) {
            int gg = i >> 9, uu = i & 511;
            int nb = ((uu >> 3) << 5) + (gg << 3) + (uu & 7);
            g_bias[nb] = bih[i] + bhh[i];
        }
    }
}

// ---------------- x-GEMM: 3-stage single-sync pipeline ----------------
__global__ void __launch_bounds__(256, 2)
gemm_x(int dummy) {
    extern __shared__ char smem[];
    const int tid = threadIdx.x;
    const int lane = tid & 31, wid = tid >> 5;
    const int wm = wid >> 2, wn = wid & 3;
    const int bn = blockIdx.x, bm = blockIdx.y;

    const __half* A = g_wx + (size_t)bm * 128 * Kz;
    const __half* B = g_wih + (size_t)bn * 128 * Kz;
    const __half* srcs[2] = {A, B};

    auto prefetch = [&](int kt, int stage) {
        int k0 = kt * 32;
        char* sbase = smem + stage * X_STAGE;
#pragma unroll
        for (int m = 0; m < 2; m++) {
#pragma unroll
            for (int j = 0; j < 2; j++) {
                int ci = tid * 2 + j;
                int row = ci >> 2, c16 = ci & 3;
                const void* g = srcs[m] + (size_t)row * Kz + k0 + c16 * 8;
                uint32_t s = smem_u32(sbase + m * MAT_BYTES + row * 80 + c16 * 16);
                CP_ASYNC16(s, g);
            }
        }
    };

    float acc[4][4][4];
#pragma unroll
    for (int a = 0; a < 4; a++)
#pragma unroll
        for (int b = 0; b < 4; b++)
#pragma unroll
            for (int c = 0; c < 4; c++) acc[a][b][c] = 0.f;

    prefetch(0, 0);
    CP_COMMIT();
    prefetch(1, 1);
    CP_COMMIT();

    int stage = 0;
    for (int kt = 0; kt < 16; kt++) {
        if (kt < 15) { CP_WAIT(1); } else { CP_WAIT(0); }
        __syncthreads();
        if (kt + 2 < 16) {
            int ns = stage + 2;
            if (ns >= 3) ns -= 3;
            prefetch(kt + 2, ns);
            CP_COMMIT();
        }
        char* sbase = smem + stage * X_STAGE;
#pragma unroll
        for (int kk = 0; kk < 2; kk++) {
            uint32_t av[4][4], bq[2][4];
            uint32_t a_off = (uint32_t)((wm * 64 + (lane & 15)) * 80 + (lane >> 4) * 16 + kk * 32);
#pragma unroll
            for (int mi = 0; mi < 4; mi++)
                LDSM4(av[mi], smem_u32(sbase + a_off + mi * 16 * 80));
            uint32_t b_off = (uint32_t)((wn * 32 + (lane >> 4) * 8 + (lane & 7)) * 80 +
                                        ((lane >> 3) & 1) * 16 + kk * 32);
#pragma unroll
            for (int p = 0; p < 2; p++)
                LDSM4(bq[p], smem_u32(sbase + MAT_BYTES + b_off + p * 16 * 80));
#pragma unroll
            for (int mi = 0; mi < 4; mi++)
#pragma unroll
                for (int ni = 0; ni < 4; ni++)
                    MMA(acc[mi][ni], av[mi], bq[ni >> 1][(ni & 1) * 2], bq[ni >> 1][(ni & 1) * 2 + 1]);
        }
        if (++stage == 3) stage = 0;
    }

    const int r0 = bm * 128 + wm * 64 + (lane >> 2);
#pragma unroll
    for (int ni = 0; ni < 4; ni++) {
        int c = bn * 128 + wn * 32 + ni * 8 + (lane & 3) * 2;
        float2 bi = *(const float2*)(g_bias + c);
#pragma unroll
        for (int mi = 0; mi < 4; mi++) {
            int r = r0 + mi * 16;
            st_cs_u32(g_gx16 + (size_t)r * G4 + c,
                      pack_h2(acc[mi][ni][0] + bi.x, acc[mi][ni][1] + bi.y));
            st_cs_u32(g_gx16 + (size_t)(r + 8) * G4 + c,
                      pack_h2(acc[mi][ni][2] + bi.x, acc[mi][ni][3] + bi.y));
        }
    }
}

// ---------------- persistent recurrence ----------------
__global__ void __launch_bounds__(256)
gemm_rec(float* __restrict__ out_enc) {
    extern __shared__ char smem[];
    const int tid = threadIdx.x;
    const int lane = tid & 31, wid = tid >> 5;
    const int wm = wid >> 2, wn = wid & 3;
    const int bn = blockIdx.x & 15, bm = blockIdx.x >> 4;
    const int swl = (lane >> 1) & 3;

    // ---- W_hh tile resident (128 gate-cols x 512 k) ----
    for (int i = tid; i < 8192; i += 256) {
        int row = i >> 6, c = i & 63;
        CP_ASYNC16(smem_u32(smem + row * BRP + c * 16),
                   g_whh + (size_t)(bn * 128 + row) * 512 + c * 8);
    }
    CP_COMMIT();

    auto pref_gx = [&](int t) {
        char* gb = smem + RGX_OFF + (t & 1) * RGX_BUF;
#pragma unroll
        for (int q = 0; q < 8; q++) {
            int ci = tid + q * 256;
            int row = ci >> 4, c = ci & 15;
            const void* g = g_gx16 + ((size_t)(bm * 128 + row) * Tz + t) * G4 + bn * 128 + c * 8;
            CP_ASYNC16(smem_u32(gb + row * RGXP + c * 16), g);
        }
    };
    pref_gx(0);
    CP_COMMIT();

    const int U = (bn * 4 + wn) * 8 + (lane & 3) * 2;

    float c_reg[4][2][2];
#pragma unroll
    for (int mi = 0; mi < 4; mi++)
#pragma unroll
        for (int h = 0; h < 2; h++) { c_reg[mi][h][0] = 0.f; c_reg[mi][h][1] = 0.f; }

    for (int t = 0; t < Tz; t++) {
        // ---- wait for all 16 producers of this bm group (16 parallel spins) ----
        if (t) {
            if (tid < 16) {
                while (ld_acq(&g_flag[bm * 16 + tid]) < (unsigned)t) { }
            }
            __syncthreads();
        }

        const __half* A = g_h2 + (size_t)(t & 1) * Bz * Hz + (size_t)bm * 128 * Hz;
        auto prefA = [&](int c, int st) {
            int k0 = c * 32;
            char* sb = smem + RA_OFF + st * RA_STAGE;
#pragma unroll
            for (int j = 0; j < 2; j++) {
                int ci = tid * 2 + j;
                int row = ci >> 2, c16 = ci & 3;
                int sw = (row >> 1) & 3;
                CP_ASYNC16(smem_u32(sb + row * 64 + ((c16 ^ sw) << 4)),
                           A + (size_t)row * Hz + k0 + c16 * 8);
            }
        };

        prefA(bn, 0);
        CP_COMMIT();
        prefA((bn + 1) & 15, 1);
        CP_COMMIT();

        float acc[4][4][4];
#pragma unroll
        for (int a = 0; a < 4; a++)
#pragma unroll
            for (int b = 0; b < 4; b++)
#pragma unroll
                for (int c = 0; c < 4; c++) acc[a][b][c] = 0.f;

        int stage = 0;
        for (int j = 0; j < 16; j++) {
            if (j < 15) { CP_WAIT(1); } else { CP_WAIT(0); }
            __syncthreads();
            if (j + 2 < 16) {
                int ns = stage + 2;
                if (ns >= 3) ns -= 3;
                prefA((bn + j + 2) & 15, ns);
                CP_COMMIT();
            }
            int c = (bn + j) & 15;
            char* sa = smem + RA_OFF + stage * RA_STAGE;
#pragma unroll
            for (int kk = 0; kk < 2; kk++) {
                uint32_t av[4][4], bq[2][4];
#pragma unroll
                for (int mi = 0; mi < 4; mi++) {
                    int row = wm * 64 + (lane & 15) + mi * 16;
                    int c16 = (lane >> 4) + kk * 2;
                    LDSM4(av[mi], smem_u32(sa + row * 64 + ((c16 ^ swl) << 4)));
                }
                uint32_t b_off = (uint32_t)((wn * 32 + (lane >> 4) * 8 + (lane & 7)) * BRP +
                                            c * 64 + kk * 32 + ((lane >> 3) & 1) * 16);
#pragma unroll
                for (int p = 0; p < 2; p++)
                    LDSM4(bq[p], smem_u32(smem + b_off + p * 16 * BRP));
#pragma unroll
                for (int mi = 0; mi < 4; mi++)
#pragma unroll
                    for (int ni = 0; ni < 4; ni++)
                        MMA(acc[mi][ni], av[mi], bq[ni >> 1][(ni & 1) * 2], bq[ni >> 1][(ni & 1) * 2 + 1]);
            }
            if (++stage == 3) stage = 0;
        }

        // ---- fused LSTM epilogue (gx from smem, c in registers) ----
        __half* hw = g_h2 + (size_t)((t + 1) & 1) * Bz * Hz;
        char* gb = smem + RGX_OFF + (t & 1) * RGX_BUF;
#pragma unroll
        for (int mi = 0; mi < 4; mi++) {
#pragma unroll
            for (int half = 0; half < 2; half++) {
                int mloc = wm * 64 + mi * 16 + half * 8 + (lane >> 2);
                int m = bm * 128 + mloc;
                int j0 = half * 2;
                const __half* gxr = (const __half*)(gb + mloc * RGXP) + wn * 32 + (lane & 3) * 2;
                float2 gI = __half22float2(*(const __half2*)(gxr + 0));
                float2 gF = __half22float2(*(const __half2*)(gxr + 8));
                float2 gG = __half22float2(*(const __half2*)(gxr + 16));
                float2 gO = __half22float2(*(const __half2*)(gxr + 24));
                float gi0 = acc[mi][0][j0] + gI.x, gi1 = acc[mi][0][j0 + 1] + gI.y;
                float gf0 = acc[mi][1][j0] + gF.x, gf1 = acc[mi][1][j0 + 1] + gF.y;
                float gg0 = acc[mi][2][j0] + gG.x, gg1 = acc[mi][2][j0 + 1] + gG.y;
                float go0 = acc[mi][3][j0] + gO.x, go1 = acc[mi][3][j0 + 1] + gO.y;
                float c20 = sigm(gf0) * c_reg[mi][half][0] + sigm(gi0) * tanh_f(gg0);
                float c21 = sigm(gf1) * c_reg[mi][half][1] + sigm(gi1) * tanh_f(gg1);
                c_reg[mi][half][0] = c20;
                c_reg[mi][half][1] = c21;
                float h20 = sigm(go0) * tanh_f(c20);
                float h21 = sigm(go1) * tanh_f(c21);
                *(float2*)(out_enc + ((size_t)m * Tz + t) * Hz + U) = make_float2(h20, h21);
                *(__half2*)(hw + (size_t)m * Hz + U) =
                    __half2(__float2half_rn(h20), __float2half_rn(h21));
            }
        }

        // ---- publish: fence, arrive, then prefetch next gx slice ----
        __threadfence();
        __syncthreads();
        if (tid == 0) atomicAdd(&g_flag[bm * 16 + bn], 1u);
        if (t + 1 < Tz) {
            pref_gx(t + 1);
            CP_COMMIT();
        }
    }
}

// ---------------- launch ----------------
extern "C" void kernel_launch(void* const* d_in, const int* in_sizes, int n_in,
                              void* d_out, int out_size) {
    const float* x      = (const float*)d_in[0];
    const float* w_ih   = (const float*)d_in[1];
    const float* w_hh   = (const float*)d_in[2];
    const float* b_ih   = (const float*)d_in[3];
    const float* b_hh   = (const float*)d_in[4];
    const float* w_attn = (const float*)d_in[5];
    (void)in_sizes; (void)n_in; (void)out_size;

    float* out_w   = (float*)d_out;
    float* out_enc = out_w + (size_t)Bz * Tz * Dz;

    static int attr_done = 0;
    if (!attr_done) {
        cudaFuncSetAttribute(gemm_x, cudaFuncAttributeMaxDynamicSharedMemorySize, X_SMEM);
        cudaFuncSetAttribute(gemm_rec, cudaFuncAttributeMaxDynamicSharedMemorySize, REC_SMEM);
        attr_done = 1;
    }

    init_kernel<<<(Bz * Hz + 255) / 256, 256>>>();
    attn_wx_kernel<<<Bz, Dz>>>(x, w_attn, out_w);
    prep_w_kernel<<<(G4 * Kz + 255) / 256, 256>>>(w_ih, w_hh, b_ih, b_hh);

    // G_x = WX @ W_ih'^T + bias   (M = 65536, N = 2048 interleaved, K = 512)
    gemm_x<<<dim3(G4 / 128, (Bz * Tz) / 128), 256, X_SMEM>>>(0);

    // persistent recurrence: all 64 steps in one launch
    gemm_rec<<<128, 256, REC_SMEM>>>(out_enc);
}